// round 6
// baseline (speedup 1.0000x reference)
#include <cuda_runtime.h>
#include <cuda_bf16.h>
#include <math.h>
#include <stdint.h>

#define HIDDEN 2048
#define BOT    64
#define NEXP   8
#define NTOK   16384

#define BM       64
#define BK       64
#define NTILES   (HIDDEN / BK)       // 32
#define THREADS  256
#define NBLK     (NTOK / BM)         // 256

// ---------------- dynamic smem layout (byte offsets) ---------------------------
#define A_HI(b)   ((b) * 8192)                // 2 x 8KB (64 rows x 128B bf16)
#define A_LO(b)   (16384 + (b) * 8192)
#define B_HI(b)   (32768 + (b) * 8192)        // 2 x 8KB (64 rows x 128B bf16)
#define B_LO(b)   (49152 + (b) * 8192)
#define O_MU      65536                       // 64 f32
#define O_RS      65792
#define O_S       66048
#define O_T       66304
#define O_WUP     66560                       // 2KB raw w_up [8][64]
#define O_LG      68608                       // 2KB logits [64][8]
#define SMEM_TOTAL 70656
#define ZSTRIDE   68

#define SWZ128(off) ((off) ^ (((off) >> 3) & 0x70))

// ---------------- device scratch (no allocations allowed) ----------------------
__device__ uint4 g_Bhi4[NTILES * 512];   // pre-swizzled bf16 hi tiles [n][k]
__device__ uint4 g_Blo4[NTILES * 512];   // lo tiles
__device__ float g_s[BOT];
__device__ float g_t[BOT];

// ---------------- PTX helpers ---------------------------------------------------
__device__ __forceinline__ uint32_t smem_u32(const void* p) {
    uint32_t a;
    asm("{ .reg .u64 t; cvta.to.shared.u64 t, %1; cvt.u32.u64 %0, t; }" : "=r"(a) : "l"(p));
    return a;
}
__device__ __forceinline__ void cpa16(uint32_t dst, const void* src) {
    asm volatile("cp.async.cg.shared.global [%0], [%1], 16;" :: "r"(dst), "l"(src));
}
#define CP_COMMIT() asm volatile("cp.async.commit_group;" ::: "memory")
#define CP_WAIT0()  asm volatile("cp.async.wait_group 0;" ::: "memory")

#define LDMX4(r, a) \
    asm volatile("ldmatrix.sync.aligned.m8n8.x4.shared.b16 {%0,%1,%2,%3}, [%4];" \
        : "=r"((r)[0]), "=r"((r)[1]), "=r"((r)[2]), "=r"((r)[3]) : "r"(a))

#define MMA16816(d, a, b0, b1) \
    asm volatile("mma.sync.aligned.m16n8k16.row.col.f32.bf16.bf16.f32 " \
        "{%0,%1,%2,%3}, {%4,%5,%6,%7}, {%8,%9}, {%0,%1,%2,%3};" \
        : "+f"((d)[0]), "+f"((d)[1]), "+f"((d)[2]), "+f"((d)[3]) \
        : "r"((a)[0]), "r"((a)[1]), "r"((a)[2]), "r"((a)[3]), "r"(b0), "r"(b1))

// ---------------- prep: split G = gamma*W into bf16 hi/lo, pre-swizzled ---------
__global__ void prep_kernel(const float* __restrict__ w_down,
                            const float* __restrict__ gamma,
                            const float* __restrict__ beta)
{
    __shared__ float red_s[8], red_t[8];
    const int n   = blockIdx.x;           // 0..63
    const int tid = threadIdx.x;          // 256
    const int k0  = tid * 8;

    float w[8], gv[8], bv[8];
    *(float4*)&w[0]  = *(const float4*)(w_down + n * HIDDEN + k0);
    *(float4*)&w[4]  = *(const float4*)(w_down + n * HIDDEN + k0 + 4);
    *(float4*)&gv[0] = *(const float4*)(gamma + k0);
    *(float4*)&gv[4] = *(const float4*)(gamma + k0 + 4);
    *(float4*)&bv[0] = *(const float4*)(beta + k0);
    *(float4*)&bv[4] = *(const float4*)(beta + k0 + 4);

    float ps = 0.f, pt = 0.f;
    uint32_t hih[4], loh[4];
    #pragma unroll
    for (int p = 0; p < 4; p++) {
        float g0 = gv[2*p] * w[2*p];
        float g1 = gv[2*p+1] * w[2*p+1];
        ps += g0 + g1;
        pt = fmaf(bv[2*p], w[2*p], pt);
        pt = fmaf(bv[2*p+1], w[2*p+1], pt);
        __nv_bfloat162 h = __floats2bfloat162_rn(g0, g1);
        float r0 = g0 - __bfloat162float(h.x);
        float r1 = g1 - __bfloat162float(h.y);
        __nv_bfloat162 l = __floats2bfloat162_rn(r0, r1);
        hih[p] = *(uint32_t*)&h;
        loh[p] = *(uint32_t*)&l;
    }
    const int tile = k0 >> 6, kk = k0 & 63;
    uint32_t off = (uint32_t)(n * 128 + kk * 2);     // 16B-aligned
    uint32_t sw  = SWZ128(off);
    *(uint4*)((char*)g_Bhi4 + tile * 8192 + sw) = make_uint4(hih[0], hih[1], hih[2], hih[3]);
    *(uint4*)((char*)g_Blo4 + tile * 8192 + sw) = make_uint4(loh[0], loh[1], loh[2], loh[3]);

    #pragma unroll
    for (int o = 16; o > 0; o >>= 1) {
        ps += __shfl_xor_sync(0xffffffffu, ps, o);
        pt += __shfl_xor_sync(0xffffffffu, pt, o);
    }
    int wi = tid >> 5, lane = tid & 31;
    if (lane == 0) { red_s[wi] = ps; red_t[wi] = pt; }
    __syncthreads();
    if (tid == 0) {
        float ss = 0.f, tt = 0.f;
        #pragma unroll
        for (int i = 0; i < 8; i++) { ss += red_s[i]; tt += red_t[i]; }
        g_s[n] = ss; g_t[n] = tt;
    }
}

// ---------------- main fused HMMA kernel ----------------------------------------
extern __shared__ char dsm[];

__global__ __launch_bounds__(THREADS, 3)
void router_kernel(const float* __restrict__ H,      // [16384][2048]
                   const float* __restrict__ w_up,   // [8][64]
                   float* __restrict__ out)          // [16384][8]
{
    const uint32_t sb  = smem_u32(dsm);
    const int tid  = threadIdx.x;
    const int wid  = tid >> 5;
    const int lane = tid & 31;
    const int wm   = wid & 1;             // rows wm*32..+32
    const int wn   = wid >> 1;            // cols wn*16..+16

    // small tables
    ((float*)(dsm + O_WUP))[tid]       = w_up[tid];
    ((float*)(dsm + O_WUP))[tid + 256] = w_up[tid + 256];
    if (tid < BOT) {
        ((float*)(dsm + O_S))[tid] = g_s[tid];
        ((float*)(dsm + O_T))[tid] = g_t[tid];
    }

    // A geometry: 4 float4/thread/tile; rows lrow+16j, k quad (tid&15)
    const int lrow = tid >> 4;
    const float* Hbase = H + ((size_t)blockIdx.x * BM + lrow) * HIDDEN + (tid & 15) * 4;
    const uint32_t sts_sw = SWZ128((uint32_t)(lrow * 128 + (tid & 15) * 8));

    // Precomputed LDSM base offsets. Row term sits in bits>=7, k term in bits 4-6,
    // so SWZ128(row + kb) == (SWZ128(row) ^ half16) ^ (s*32). One LOP per LDSM.
    const uint32_t half16 = (uint32_t)((lane >> 4) * 16);
    uint32_t aoff[2], boff;
    #pragma unroll
    for (int mi = 0; mi < 2; mi++)
        aoff[mi] = SWZ128((uint32_t)((wm * 32 + mi * 16 + (lane & 15)) * 128)) ^ half16;
    boff = SWZ128((uint32_t)((wn * 16 + (lane & 15)) * 128)) ^ half16;

    float acc[2][2][4];
    #pragma unroll
    for (int mi = 0; mi < 2; mi++)
        #pragma unroll
        for (int ni = 0; ni < 2; ni++)
            #pragma unroll
            for (int r = 0; r < 4; r++) acc[mi][ni][r] = 0.f;

    float psum[4] = {0.f, 0.f, 0.f, 0.f};
    float psq[4]  = {0.f, 0.f, 0.f, 0.f};
    float4 pf[4];

    // prologue: B0 via cp.async, A0 into regs
    cpa16(sb + B_HI(0) + tid * 16,         &g_Bhi4[tid]);
    cpa16(sb + B_HI(0) + (tid + 256) * 16, &g_Bhi4[tid + 256]);
    cpa16(sb + B_LO(0) + tid * 16,         &g_Blo4[tid]);
    cpa16(sb + B_LO(0) + (tid + 256) * 16, &g_Blo4[tid + 256]);
    CP_COMMIT();
    #pragma unroll
    for (int j = 0; j < 4; j++)
        pf[j] = *(const float4*)(Hbase + (size_t)j * 16 * HIDDEN);

    #pragma unroll 1
    for (int t = 0; t < NTILES; t++) {
        const int buf = t & 1;
        // ---- convert A_t regs -> smem ----
        #pragma unroll
        for (int j = 0; j < 4; j++) {
            float4 v = pf[j];
            psum[j] += (v.x + v.y) + (v.z + v.w);
            psq[j]  = fmaf(v.x, v.x, psq[j]); psq[j] = fmaf(v.y, v.y, psq[j]);
            psq[j]  = fmaf(v.z, v.z, psq[j]); psq[j] = fmaf(v.w, v.w, psq[j]);
            __nv_bfloat162 h01 = __floats2bfloat162_rn(v.x, v.y);
            __nv_bfloat162 h23 = __floats2bfloat162_rn(v.z, v.w);
            float rx = v.x - __bfloat162float(h01.x);
            float ry = v.y - __bfloat162float(h01.y);
            float rz = v.z - __bfloat162float(h23.x);
            float rw = v.w - __bfloat162float(h23.y);
            __nv_bfloat162 l01 = __floats2bfloat162_rn(rx, ry);
            __nv_bfloat162 l23 = __floats2bfloat162_rn(rz, rw);
            uint32_t sw = sts_sw + (uint32_t)(j * 2048);
            *(uint2*)(dsm + A_HI(buf) + sw) = make_uint2(*(uint32_t*)&h01, *(uint32_t*)&h23);
            *(uint2*)(dsm + A_LO(buf) + sw) = make_uint2(*(uint32_t*)&l01, *(uint32_t*)&l23);
        }
        // ---- prefetch A_{t+1} (consumed next iter) ----
        if (t + 1 < NTILES) {
            const float* hp = Hbase + (t + 1) * BK;
            #pragma unroll
            for (int j = 0; j < 4; j++)
                pf[j] = *(const float4*)(hp + (size_t)j * 16 * HIDDEN);
        }
        CP_WAIT0();                 // B_t landed
        __syncthreads();            // A_t visible; MMA_{t-1} fully done
        // ---- issue B_{t+1} (safe: post-barrier) ----
        if (t + 1 < NTILES) {
            const uint4* srcH = g_Bhi4 + (t + 1) * 512;
            const uint4* srcL = g_Blo4 + (t + 1) * 512;
            const int nb = buf ^ 1;
            cpa16(sb + B_HI(nb) + tid * 16,         srcH + tid);
            cpa16(sb + B_HI(nb) + (tid + 256) * 16, srcH + tid + 256);
            cpa16(sb + B_LO(nb) + tid * 16,         srcL + tid);
            cpa16(sb + B_LO(nb) + (tid + 256) * 16, srcL + tid + 256);
            CP_COMMIT();
        }
        // ---- MMA over buf ----
        const uint32_t ab_hi = sb + A_HI(buf), ab_lo = sb + A_LO(buf);
        const uint32_t bb_hi = sb + B_HI(buf), bb_lo = sb + B_LO(buf);
        #pragma unroll
        for (int s = 0; s < 4; s++) {
            const uint32_t ks = (uint32_t)(s * 32);
            uint32_t ah[2][4], al[2][4], bh[4], bl[4];
            #pragma unroll
            for (int mi = 0; mi < 2; mi++) {
                LDMX4(ah[mi], ab_hi + (aoff[mi] ^ ks));
                LDMX4(al[mi], ab_lo + (aoff[mi] ^ ks));
            }
            LDMX4(bh, bb_hi + (boff ^ ks));
            LDMX4(bl, bb_lo + (boff ^ ks));
            #pragma unroll
            for (int mi = 0; mi < 2; mi++)
                #pragma unroll
                for (int ni = 0; ni < 2; ni++) {
                    MMA16816(acc[mi][ni], ah[mi], bh[ni], bh[ni + 2]);
                    MMA16816(acc[mi][ni], ah[mi], bl[ni], bl[ni + 2]);
                    MMA16816(acc[mi][ni], al[mi], bh[ni], bh[ni + 2]);
                }
        }
    }
    __syncthreads();    // all MMA done; A region reusable as z-buffer

    // ---- LN stats: groups of 16 consecutive lanes share a row ----
    #pragma unroll
    for (int o = 1; o < 16; o <<= 1) {
        #pragma unroll
        for (int j = 0; j < 4; j++) {
            psum[j] += __shfl_xor_sync(0xffffffffu, psum[j], o);
            psq[j]  += __shfl_xor_sync(0xffffffffu, psq[j], o);
        }
    }
    if ((tid & 15) == 0) {
        #pragma unroll
        for (int j = 0; j < 4; j++) {
            int row = j * 16 + lrow;
            float mu  = psum[j] * (1.f / HIDDEN);
            float var = psq[j] * (1.f / HIDDEN) - mu * mu;
            ((float*)(dsm + O_MU))[row] = mu;
            ((float*)(dsm + O_RS))[row] = rsqrtf(var + 1e-5f);
        }
    }
    __syncthreads();

    // ---- epilogue: LN-correct + SiLU -> z buffer ----
    {
        float* zb = (float*)dsm;
        const float* muA = (const float*)(dsm + O_MU);
        const float* rsA = (const float*)(dsm + O_RS);
        const float* sA  = (const float*)(dsm + O_S);
        const float* tA  = (const float*)(dsm + O_T);
        #pragma unroll
        for (int mi = 0; mi < 2; mi++) {
            int r0 = wm * 32 + mi * 16 + (lane >> 2);
            float mu0 = muA[r0], rs0 = rsA[r0];
            float mu1 = muA[r0 + 8], rs1 = rsA[r0 + 8];
            #pragma unroll
            for (int ni = 0; ni < 2; ni++) {
                int c0 = wn * 16 + ni * 8 + (lane & 3) * 2;
                float s0 = sA[c0], s1 = sA[c0 + 1];
                float t0 = tA[c0], t1 = tA[c0 + 1];
                float p00 = rs0 * (acc[mi][ni][0] - mu0 * s0) + t0;
                float p01 = rs0 * (acc[mi][ni][1] - mu0 * s1) + t1;
                float p10 = rs1 * (acc[mi][ni][2] - mu1 * s0) + t0;
                float p11 = rs1 * (acc[mi][ni][3] - mu1 * s1) + t1;
                float z00 = p00 / (1.f + __expf(-p00));
                float z01 = p01 / (1.f + __expf(-p01));
                float z10 = p10 / (1.f + __expf(-p10));
                float z11 = p11 / (1.f + __expf(-p11));
                *(float2*)&zb[r0 * ZSTRIDE + c0]       = make_float2(z00, z01);
                *(float2*)&zb[(r0 + 8) * ZSTRIDE + c0] = make_float2(z10, z11);
            }
        }
    }
    __syncthreads();

    // ---- router GEMM: thread = (token m, expert pair eg) ----
    {
        const int m = tid & 63, eg = tid >> 6;
        const float* zr = (const float*)dsm + m * ZSTRIDE;
        const float* w0 = (const float*)(dsm + O_WUP) + eg * 128;
        const float* w1 = w0 + 64;
        float l0 = 0.f, l1 = 0.f;
        #pragma unroll
        for (int d4 = 0; d4 < 16; d4++) {
            float4 zv = ((const float4*)zr)[d4];
            float4 wa = ((const float4*)w0)[d4];
            float4 wb = ((const float4*)w1)[d4];
            l0 = fmaf(zv.x, wa.x, l0); l0 = fmaf(zv.y, wa.y, l0);
            l0 = fmaf(zv.z, wa.z, l0); l0 = fmaf(zv.w, wa.w, l0);
            l1 = fmaf(zv.x, wb.x, l1); l1 = fmaf(zv.y, wb.y, l1);
            l1 = fmaf(zv.z, wb.z, l1); l1 = fmaf(zv.w, wb.w, l1);
        }
        ((float*)(dsm + O_LG))[m * 8 + eg * 2]     = l0;
        ((float*)(dsm + O_LG))[m * 8 + eg * 2 + 1] = l1;
    }
    __syncthreads();

    // ---- top-2 softmax (first-index tie-break matches jax.lax.top_k) ----
    if (tid < BM) {
        const float* lp = (const float*)(dsm + O_LG) + tid * 8;
        float lg[8];
        #pragma unroll
        for (int e = 0; e < 8; e++) lg[e] = lp[e];
        int i1 = 0; float m1 = lg[0];
        #pragma unroll
        for (int e = 1; e < 8; e++) if (lg[e] > m1) { m1 = lg[e]; i1 = e; }
        int i2 = -1; float m2 = -3.4e38f;
        #pragma unroll
        for (int e = 0; e < 8; e++) if (e != i1 && lg[e] > m2) { m2 = lg[e]; i2 = e; }
        float p1 = 1.f / (1.f + __expf(m2 - m1));
        float p2 = 1.f - p1;
        float o[8];
        #pragma unroll
        for (int e = 0; e < 8; e++) o[e] = (e == i1) ? p1 : (e == i2) ? p2 : 0.f;
        float* op = out + ((size_t)blockIdx.x * BM + tid) * NEXP;
        *(float4*)op       = make_float4(o[0], o[1], o[2], o[3]);
        *(float4*)(op + 4) = make_float4(o[4], o[5], o[6], o[7]);
    }
}

// ---------------- launch --------------------------------------------------------
extern "C" void kernel_launch(void* const* d_in, const int* in_sizes, int n_in,
                              void* d_out, int out_size)
{
    (void)in_sizes; (void)n_in; (void)out_size;
    const float* hs     = (const float*)d_in[0];
    const float* w_down = (const float*)d_in[1];
    const float* w_up   = (const float*)d_in[2];
    const float* gamma  = (const float*)d_in[3];
    const float* beta   = (const float*)d_in[4];
    float* out = (float*)d_out;

    static int attr_done = 0;
    if (!attr_done) {
        cudaFuncSetAttribute(router_kernel, cudaFuncAttributeMaxDynamicSharedMemorySize, SMEM_TOTAL);
        attr_done = 1;
    }
    prep_kernel<<<BOT, THREADS>>>(w_down, gamma, beta);
    router_kernel<<<NBLK, THREADS, SMEM_TOTAL>>>(hs, w_up, out);
}

// round 7
// speedup vs baseline: 1.0005x; 1.0005x over previous
#include <cuda_runtime.h>
#include <cuda_bf16.h>
#include <math.h>
#include <stdint.h>

#define HIDDEN 2048
#define BOT    64
#define NEXP   8
#define NTOK   16384

#define BM       64
#define BK       64
#define NTILES   (HIDDEN / BK)       // 32
#define THREADS  256
#define NBLK     (NTOK / BM)         // 256

// ---------------- dynamic smem layout (byte offsets) ---------------------------
#define S_F32(b)  ((b) * 16384)               // 2 x 16KB staged A f32 (thread-private slots)
#define A_HI(b)   (32768 + (b) * 8192)        // 2 x 8KB (64 rows x 128B bf16)
#define A_LO(b)   (49152 + (b) * 8192)
#define B_HI(b)   (65536 + (b) * 8192)
#define B_LO(b)   (81920 + (b) * 8192)
#define O_MU      98304                       // 64 f32
#define O_RS      98560
#define O_S       98816
#define O_T       99072
#define O_WUP     99328                       // 2KB raw w_up [8][64]
#define O_LG      101376                      // 2KB logits [64][8]
#define SMEM_TOTAL 103424
#define ZSTRIDE   68

#define SWZ128(off) ((off) ^ (((off) >> 3) & 0x70))

// ---------------- device scratch (no allocations allowed) ----------------------
__device__ uint4 g_Bhi4[NTILES * 512];   // pre-swizzled bf16 hi tiles [n][k]
__device__ uint4 g_Blo4[NTILES * 512];   // lo tiles
__device__ float g_s[BOT];
__device__ float g_t[BOT];

// ---------------- PTX helpers ---------------------------------------------------
__device__ __forceinline__ uint32_t smem_u32(const void* p) {
    uint32_t a;
    asm("{ .reg .u64 t; cvta.to.shared.u64 t, %1; cvt.u32.u64 %0, t; }" : "=r"(a) : "l"(p));
    return a;
}
__device__ __forceinline__ void cpa16(uint32_t dst, const void* src) {
    asm volatile("cp.async.cg.shared.global [%0], [%1], 16;" :: "r"(dst), "l"(src));
}
#define CP_COMMIT() asm volatile("cp.async.commit_group;" ::: "memory")
#define CP_WAIT1()  asm volatile("cp.async.wait_group 1;" ::: "memory")

#define LDMX4(r, a) \
    asm volatile("ldmatrix.sync.aligned.m8n8.x4.shared.b16 {%0,%1,%2,%3}, [%4];" \
        : "=r"((r)[0]), "=r"((r)[1]), "=r"((r)[2]), "=r"((r)[3]) : "r"(a))

#define MMA16816(d, a, b0, b1) \
    asm volatile("mma.sync.aligned.m16n8k16.row.col.f32.bf16.bf16.f32 " \
        "{%0,%1,%2,%3}, {%4,%5,%6,%7}, {%8,%9}, {%0,%1,%2,%3};" \
        : "+f"((d)[0]), "+f"((d)[1]), "+f"((d)[2]), "+f"((d)[3]) \
        : "r"((a)[0]), "r"((a)[1]), "r"((a)[2]), "r"((a)[3]), "r"(b0), "r"(b1))

// ---------------- prep: split G = gamma*W into bf16 hi/lo, pre-swizzled ---------
__global__ void prep_kernel(const float* __restrict__ w_down,
                            const float* __restrict__ gamma,
                            const float* __restrict__ beta)
{
    __shared__ float red_s[8], red_t[8];
    const int n   = blockIdx.x;           // 0..63
    const int tid = threadIdx.x;          // 256
    const int k0  = tid * 8;

    float w[8], gv[8], bv[8];
    *(float4*)&w[0]  = *(const float4*)(w_down + n * HIDDEN + k0);
    *(float4*)&w[4]  = *(const float4*)(w_down + n * HIDDEN + k0 + 4);
    *(float4*)&gv[0] = *(const float4*)(gamma + k0);
    *(float4*)&gv[4] = *(const float4*)(gamma + k0 + 4);
    *(float4*)&bv[0] = *(const float4*)(beta + k0);
    *(float4*)&bv[4] = *(const float4*)(beta + k0 + 4);

    float ps = 0.f, pt = 0.f;
    uint32_t hih[4], loh[4];
    #pragma unroll
    for (int p = 0; p < 4; p++) {
        float g0 = gv[2*p] * w[2*p];
        float g1 = gv[2*p+1] * w[2*p+1];
        ps += g0 + g1;
        pt = fmaf(bv[2*p], w[2*p], pt);
        pt = fmaf(bv[2*p+1], w[2*p+1], pt);
        __nv_bfloat162 h = __floats2bfloat162_rn(g0, g1);
        float r0 = g0 - __bfloat162float(h.x);
        float r1 = g1 - __bfloat162float(h.y);
        __nv_bfloat162 l = __floats2bfloat162_rn(r0, r1);
        hih[p] = *(uint32_t*)&h;
        loh[p] = *(uint32_t*)&l;
    }
    const int tile = k0 >> 6, kk = k0 & 63;
    uint32_t off = (uint32_t)(n * 128 + kk * 2);     // 16B-aligned
    uint32_t sw  = SWZ128(off);
    *(uint4*)((char*)g_Bhi4 + tile * 8192 + sw) = make_uint4(hih[0], hih[1], hih[2], hih[3]);
    *(uint4*)((char*)g_Blo4 + tile * 8192 + sw) = make_uint4(loh[0], loh[1], loh[2], loh[3]);

    #pragma unroll
    for (int o = 16; o > 0; o >>= 1) {
        ps += __shfl_xor_sync(0xffffffffu, ps, o);
        pt += __shfl_xor_sync(0xffffffffu, pt, o);
    }
    int wi = tid >> 5, lane = tid & 31;
    if (lane == 0) { red_s[wi] = ps; red_t[wi] = pt; }
    __syncthreads();
    if (tid == 0) {
        float ss = 0.f, tt = 0.f;
        #pragma unroll
        for (int i = 0; i < 8; i++) { ss += red_s[i]; tt += red_t[i]; }
        g_s[n] = ss; g_t[n] = tt;
    }
}

// ---------------- main fused HMMA kernel ----------------------------------------
extern __shared__ char dsm[];

__global__ __launch_bounds__(THREADS, 2)
void router_kernel(const float* __restrict__ H,      // [16384][2048]
                   const float* __restrict__ w_up,   // [8][64]
                   float* __restrict__ out)          // [16384][8]
{
    const uint32_t sb  = smem_u32(dsm);
    const int tid  = threadIdx.x;
    const int wid  = tid >> 5;
    const int lane = tid & 31;
    const int wm   = wid & 1;             // rows wm*32..+32
    const int wn   = wid >> 1;            // cols wn*16..+16

    // small tables
    ((float*)(dsm + O_WUP))[tid]       = w_up[tid];
    ((float*)(dsm + O_WUP))[tid + 256] = w_up[tid + 256];
    if (tid < BOT) {
        ((float*)(dsm + O_S))[tid] = g_s[tid];
        ((float*)(dsm + O_T))[tid] = g_t[tid];
    }

    // A geometry: 4 float4/thread/tile; rows lrow+16j, k quad (tid&15)
    const int lrow = tid >> 4;
    const float* Hbase = H + ((size_t)blockIdx.x * BM + lrow) * HIDDEN + (tid & 15) * 4;
    const uint32_t sts_sw = SWZ128((uint32_t)(lrow * 128 + (tid & 15) * 8));
    const uint32_t stg16  = (uint32_t)(tid * 16);    // thread-private staging slot (per j: +4096)

    // Hoisted LDSM offsets: SWZ128(row + kb) == (SWZ128(row) ^ half16) ^ (s*32)
    const uint32_t half16 = (uint32_t)((lane >> 4) * 16);
    uint32_t aoff[2], boff;
    #pragma unroll
    for (int mi = 0; mi < 2; mi++)
        aoff[mi] = SWZ128((uint32_t)((wm * 32 + mi * 16 + (lane & 15)) * 128)) ^ half16;
    boff = SWZ128((uint32_t)((wn * 16 + (lane & 15)) * 128)) ^ half16;

    float acc[2][2][4];
    #pragma unroll
    for (int mi = 0; mi < 2; mi++)
        #pragma unroll
        for (int ni = 0; ni < 2; ni++)
            #pragma unroll
            for (int r = 0; r < 4; r++) acc[mi][ni][r] = 0.f;

    float psum[4] = {0.f, 0.f, 0.f, 0.f};
    float psq[4]  = {0.f, 0.f, 0.f, 0.f};
    uint4 pb[4];

    // prologue: stage A[0], A[1] via cp.async (one group each); B[0] into regs
    #pragma unroll
    for (int j = 0; j < 4; j++)
        cpa16(sb + S_F32(0) + stg16 + j * 4096, Hbase + (size_t)j * 16 * HIDDEN);
    CP_COMMIT();
    #pragma unroll
    for (int j = 0; j < 4; j++)
        cpa16(sb + S_F32(1) + stg16 + j * 4096, Hbase + BK + (size_t)j * 16 * HIDDEN);
    CP_COMMIT();
    pb[0] = g_Bhi4[tid];        pb[1] = g_Bhi4[256 + tid];
    pb[2] = g_Blo4[tid];        pb[3] = g_Blo4[256 + tid];

    #pragma unroll 1
    for (int t = 0; t < NTILES; t++) {
        const int buf = t & 1;
        CP_WAIT1();                 // A f32 tile t staged
        // ---- convert staged A_t (thread-private LDS) -> hi/lo smem ----
        #pragma unroll
        for (int j = 0; j < 4; j++) {
            float4 v = *(const float4*)(dsm + S_F32(buf) + stg16 + j * 4096);
            psum[j] += (v.x + v.y) + (v.z + v.w);
            psq[j]  = fmaf(v.x, v.x, psq[j]); psq[j] = fmaf(v.y, v.y, psq[j]);
            psq[j]  = fmaf(v.z, v.z, psq[j]); psq[j] = fmaf(v.w, v.w, psq[j]);
            __nv_bfloat162 h01 = __floats2bfloat162_rn(v.x, v.y);
            __nv_bfloat162 h23 = __floats2bfloat162_rn(v.z, v.w);
            float rx = v.x - __bfloat162float(h01.x);
            float ry = v.y - __bfloat162float(h01.y);
            float rz = v.z - __bfloat162float(h23.x);
            float rw = v.w - __bfloat162float(h23.y);
            __nv_bfloat162 l01 = __floats2bfloat162_rn(rx, ry);
            __nv_bfloat162 l23 = __floats2bfloat162_rn(rz, rw);
            uint32_t sw = sts_sw + (uint32_t)(j * 2048);
            *(uint2*)(dsm + A_HI(buf) + sw) = make_uint2(*(uint32_t*)&h01, *(uint32_t*)&h23);
            *(uint2*)(dsm + A_LO(buf) + sw) = make_uint2(*(uint32_t*)&l01, *(uint32_t*)&l23);
        }
        // ---- restage A[t+2] into S(buf): only this thread ever touches these
        //      addresses, and its LDS reads above are already complete ----
        if (t + 2 < NTILES) {
            const float* hp = Hbase + (t + 2) * BK;
            #pragma unroll
            for (int j = 0; j < 4; j++)
                cpa16(sb + S_F32(buf) + stg16 + j * 4096, hp + (size_t)j * 16 * HIDDEN);
        }
        CP_COMMIT();                // always commit to keep group accounting aligned
        // ---- B_t regs -> smem ----
        *(uint4*)(dsm + B_HI(buf) + tid * 16)         = pb[0];
        *(uint4*)(dsm + B_HI(buf) + (256 + tid) * 16) = pb[1];
        *(uint4*)(dsm + B_LO(buf) + tid * 16)         = pb[2];
        *(uint4*)(dsm + B_LO(buf) + (256 + tid) * 16) = pb[3];
        __syncthreads();            // A_t/B_t visible; MMA_{t-1} fully done
        // ---- prefetch B[t+1] (L2-resident; consumed next iteration) ----
        if (t + 1 < NTILES) {
            const uint4* srcH = g_Bhi4 + (t + 1) * 512;
            const uint4* srcL = g_Blo4 + (t + 1) * 512;
            pb[0] = srcH[tid]; pb[1] = srcH[tid + 256];
            pb[2] = srcL[tid]; pb[3] = srcL[tid + 256];
        }
        // ---- MMA over buf ----
        const uint32_t ab_hi = sb + A_HI(buf), ab_lo = sb + A_LO(buf);
        const uint32_t bb_hi = sb + B_HI(buf), bb_lo = sb + B_LO(buf);
        #pragma unroll
        for (int s = 0; s < 4; s++) {
            const uint32_t ks = (uint32_t)(s * 32);
            uint32_t ah[2][4], al[2][4], bh[4], bl[4];
            #pragma unroll
            for (int mi = 0; mi < 2; mi++) {
                LDMX4(ah[mi], ab_hi + (aoff[mi] ^ ks));
                LDMX4(al[mi], ab_lo + (aoff[mi] ^ ks));
            }
            LDMX4(bh, bb_hi + (boff ^ ks));
            LDMX4(bl, bb_lo + (boff ^ ks));
            #pragma unroll
            for (int mi = 0; mi < 2; mi++)
                #pragma unroll
                for (int ni = 0; ni < 2; ni++) {
                    MMA16816(acc[mi][ni], ah[mi], bh[ni], bh[ni + 2]);
                    MMA16816(acc[mi][ni], ah[mi], bl[ni], bl[ni + 2]);
                    MMA16816(acc[mi][ni], al[mi], bh[ni], bh[ni + 2]);
                }
        }
    }
    __syncthreads();    // all MMA done; staging region reusable as z-buffer

    // ---- LN stats: groups of 16 consecutive lanes share a row ----
    #pragma unroll
    for (int o = 1; o < 16; o <<= 1) {
        #pragma unroll
        for (int j = 0; j < 4; j++) {
            psum[j] += __shfl_xor_sync(0xffffffffu, psum[j], o);
            psq[j]  += __shfl_xor_sync(0xffffffffu, psq[j], o);
        }
    }
    if ((tid & 15) == 0) {
        #pragma unroll
        for (int j = 0; j < 4; j++) {
            int row = j * 16 + lrow;
            float mu  = psum[j] * (1.f / HIDDEN);
            float var = psq[j] * (1.f / HIDDEN) - mu * mu;
            ((float*)(dsm + O_MU))[row] = mu;
            ((float*)(dsm + O_RS))[row] = rsqrtf(var + 1e-5f);
        }
    }
    __syncthreads();

    // ---- epilogue: LN-correct + SiLU -> z buffer (reuses staging region) ----
    {
        float* zb = (float*)dsm;
        const float* muA = (const float*)(dsm + O_MU);
        const float* rsA = (const float*)(dsm + O_RS);
        const float* sA  = (const float*)(dsm + O_S);
        const float* tA  = (const float*)(dsm + O_T);
        #pragma unroll
        for (int mi = 0; mi < 2; mi++) {
            int r0 = wm * 32 + mi * 16 + (lane >> 2);
            float mu0 = muA[r0], rs0 = rsA[r0];
            float mu1 = muA[r0 + 8], rs1 = rsA[r0 + 8];
            #pragma unroll
            for (int ni = 0; ni < 2; ni++) {
                int c0 = wn * 16 + ni * 8 + (lane & 3) * 2;
                float s0 = sA[c0], s1 = sA[c0 + 1];
                float t0 = tA[c0], t1 = tA[c0 + 1];
                float p00 = rs0 * (acc[mi][ni][0] - mu0 * s0) + t0;
                float p01 = rs0 * (acc[mi][ni][1] - mu0 * s1) + t1;
                float p10 = rs1 * (acc[mi][ni][2] - mu1 * s0) + t0;
                float p11 = rs1 * (acc[mi][ni][3] - mu1 * s1) + t1;
                float z00 = p00 / (1.f + __expf(-p00));
                float z01 = p01 / (1.f + __expf(-p01));
                float z10 = p10 / (1.f + __expf(-p10));
                float z11 = p11 / (1.f + __expf(-p11));
                *(float2*)&zb[r0 * ZSTRIDE + c0]       = make_float2(z00, z01);
                *(float2*)&zb[(r0 + 8) * ZSTRIDE + c0] = make_float2(z10, z11);
            }
        }
    }
    __syncthreads();

    // ---- router GEMM: thread = (token m, expert pair eg) ----
    {
        const int m = tid & 63, eg = tid >> 6;
        const float* zr = (const float*)dsm + m * ZSTRIDE;
        const float* w0 = (const float*)(dsm + O_WUP) + eg * 128;
        const float* w1 = w0 + 64;
        float l0 = 0.f, l1 = 0.f;
        #pragma unroll
        for (int d4 = 0; d4 < 16; d4++) {
            float4 zv = ((const float4*)zr)[d4];
            float4 wa = ((const float4*)w0)[d4];
            float4 wb = ((const float4*)w1)[d4];
            l0 = fmaf(zv.x, wa.x, l0); l0 = fmaf(zv.y, wa.y, l0);
            l0 = fmaf(zv.z, wa.z, l0); l0 = fmaf(zv.w, wa.w, l0);
            l1 = fmaf(zv.x, wb.x, l1); l1 = fmaf(zv.y, wb.y, l1);
            l1 = fmaf(zv.z, wb.z, l1); l1 = fmaf(zv.w, wb.w, l1);
        }
        ((float*)(dsm + O_LG))[m * 8 + eg * 2]     = l0;
        ((float*)(dsm + O_LG))[m * 8 + eg * 2 + 1] = l1;
    }
    __syncthreads();

    // ---- top-2 softmax (first-index tie-break matches jax.lax.top_k) ----
    if (tid < BM) {
        const float* lp = (const float*)(dsm + O_LG) + tid * 8;
        float lg[8];
        #pragma unroll
        for (int e = 0; e < 8; e++) lg[e] = lp[e];
        int i1 = 0; float m1 = lg[0];
        #pragma unroll
        for (int e = 1; e < 8; e++) if (lg[e] > m1) { m1 = lg[e]; i1 = e; }
        int i2 = -1; float m2 = -3.4e38f;
        #pragma unroll
        for (int e = 0; e < 8; e++) if (e != i1 && lg[e] > m2) { m2 = lg[e]; i2 = e; }
        float p1 = 1.f / (1.f + __expf(m2 - m1));
        float p2 = 1.f - p1;
        float o[8];
        #pragma unroll
        for (int e = 0; e < 8; e++) o[e] = (e == i1) ? p1 : (e == i2) ? p2 : 0.f;
        float* op = out + ((size_t)blockIdx.x * BM + tid) * NEXP;
        *(float4*)op       = make_float4(o[0], o[1], o[2], o[3]);
        *(float4*)(op + 4) = make_float4(o[4], o[5], o[6], o[7]);
    }
}

// ---------------- launch --------------------------------------------------------
extern "C" void kernel_launch(void* const* d_in, const int* in_sizes, int n_in,
                              void* d_out, int out_size)
{
    (void)in_sizes; (void)n_in; (void)out_size;
    const float* hs     = (const float*)d_in[0];
    const float* w_down = (const float*)d_in[1];
    const float* w_up   = (const float*)d_in[2];
    const float* gamma  = (const float*)d_in[3];
    const float* beta   = (const float*)d_in[4];
    float* out = (float*)d_out;

    static int attr_done = 0;
    if (!attr_done) {
        cudaFuncSetAttribute(router_kernel, cudaFuncAttributeMaxDynamicSharedMemorySize, SMEM_TOTAL);
        attr_done = 1;
    }
    prep_kernel<<<BOT, THREADS>>>(w_down, gamma, beta);
    router_kernel<<<NBLK, THREADS, SMEM_TOTAL>>>(hs, w_up, out);
}

// round 8
// speedup vs baseline: 1.1032x; 1.1026x over previous
#include <cuda_runtime.h>
#include <cuda_bf16.h>
#include <math.h>
#include <stdint.h>

#define HIDDEN 2048
#define BOT    64
#define NEXP   8
#define NTOK   16384

#define BM       64
#define BK       64
#define NTILES   (HIDDEN / BK)       // 32
#define THREADS  256
#define NBLK     (NTOK / BM)         // 256

// ---------------- dynamic smem layout (byte offsets) ---------------------------
#define A_HI(b)   ((b) * 8192)                // 2 x 8KB (64 rows x 128B bf16)
#define A_LO(b)   (16384 + (b) * 8192)
#define B_HI(b)   (32768 + (b) * 8192)        // 2 x 8KB
#define B_LO(b)   (49152 + (b) * 8192)
#define O_PART    32768                       // 16KB k-partials (reuses B region post-loop)
#define O_MU      65536                       // 64 f32
#define O_RS      65792
#define O_S       66048
#define O_T       66304
#define O_WUP     66560                       // 2KB raw w_up [8][64]
#define O_LG      68608                       // 2KB logits [64][8]
#define SMEM_TOTAL 70656
#define ZSTRIDE   68

#define SWZ128(off) ((off) ^ (((off) >> 3) & 0x70))

// ---------------- device scratch (no allocations allowed) ----------------------
__device__ uint4 g_Bhi4[NTILES * 512];   // pre-swizzled bf16 hi tiles [n][k]
__device__ uint4 g_Blo4[NTILES * 512];   // lo tiles
__device__ float g_s[BOT];
__device__ float g_t[BOT];

// ---------------- PTX helpers ---------------------------------------------------
__device__ __forceinline__ uint32_t smem_u32(const void* p) {
    uint32_t a;
    asm("{ .reg .u64 t; cvta.to.shared.u64 t, %1; cvt.u32.u64 %0, t; }" : "=r"(a) : "l"(p));
    return a;
}
__device__ __forceinline__ void cpa16(uint32_t dst, const void* src) {
    asm volatile("cp.async.cg.shared.global [%0], [%1], 16;" :: "r"(dst), "l"(src));
}
#define CP_COMMIT() asm volatile("cp.async.commit_group;" ::: "memory")
#define CP_WAIT0()  asm volatile("cp.async.wait_group 0;" ::: "memory")

#define LDMX4(r, a) \
    asm volatile("ldmatrix.sync.aligned.m8n8.x4.shared.b16 {%0,%1,%2,%3}, [%4];" \
        : "=r"((r)[0]), "=r"((r)[1]), "=r"((r)[2]), "=r"((r)[3]) : "r"(a))

#define MMA16816(d, a, b0, b1) \
    asm volatile("mma.sync.aligned.m16n8k16.row.col.f32.bf16.bf16.f32 " \
        "{%0,%1,%2,%3}, {%4,%5,%6,%7}, {%8,%9}, {%0,%1,%2,%3};" \
        : "+f"((d)[0]), "+f"((d)[1]), "+f"((d)[2]), "+f"((d)[3]) \
        : "r"((a)[0]), "r"((a)[1]), "r"((a)[2]), "r"((a)[3]), "r"(b0), "r"(b1))

// ---------------- prep: split G = gamma*W into bf16 hi/lo, pre-swizzled ---------
__global__ void prep_kernel(const float* __restrict__ w_down,
                            const float* __restrict__ gamma,
                            const float* __restrict__ beta)
{
    __shared__ float red_s[8], red_t[8];
    const int n   = blockIdx.x;           // 0..63
    const int tid = threadIdx.x;          // 256
    const int k0  = tid * 8;

    float w[8], gv[8], bv[8];
    *(float4*)&w[0]  = *(const float4*)(w_down + n * HIDDEN + k0);
    *(float4*)&w[4]  = *(const float4*)(w_down + n * HIDDEN + k0 + 4);
    *(float4*)&gv[0] = *(const float4*)(gamma + k0);
    *(float4*)&gv[4] = *(const float4*)(gamma + k0 + 4);
    *(float4*)&bv[0] = *(const float4*)(beta + k0);
    *(float4*)&bv[4] = *(const float4*)(beta + k0 + 4);

    float ps = 0.f, pt = 0.f;
    uint32_t hih[4], loh[4];
    #pragma unroll
    for (int p = 0; p < 4; p++) {
        float g0 = gv[2*p] * w[2*p];
        float g1 = gv[2*p+1] * w[2*p+1];
        ps += g0 + g1;
        pt = fmaf(bv[2*p], w[2*p], pt);
        pt = fmaf(bv[2*p+1], w[2*p+1], pt);
        __nv_bfloat162 h = __floats2bfloat162_rn(g0, g1);
        float r0 = g0 - __bfloat162float(h.x);
        float r1 = g1 - __bfloat162float(h.y);
        __nv_bfloat162 l = __floats2bfloat162_rn(r0, r1);
        hih[p] = *(uint32_t*)&h;
        loh[p] = *(uint32_t*)&l;
    }
    const int tile = k0 >> 6, kk = k0 & 63;
    uint32_t off = (uint32_t)(n * 128 + kk * 2);     // 16B-aligned
    uint32_t sw  = SWZ128(off);
    *(uint4*)((char*)g_Bhi4 + tile * 8192 + sw) = make_uint4(hih[0], hih[1], hih[2], hih[3]);
    *(uint4*)((char*)g_Blo4 + tile * 8192 + sw) = make_uint4(loh[0], loh[1], loh[2], loh[3]);

    #pragma unroll
    for (int o = 16; o > 0; o >>= 1) {
        ps += __shfl_xor_sync(0xffffffffu, ps, o);
        pt += __shfl_xor_sync(0xffffffffu, pt, o);
    }
    int wi = tid >> 5, lane = tid & 31;
    if (lane == 0) { red_s[wi] = ps; red_t[wi] = pt; }
    __syncthreads();
    if (tid == 0) {
        float ss = 0.f, tt = 0.f;
        #pragma unroll
        for (int i = 0; i < 8; i++) { ss += red_s[i]; tt += red_t[i]; }
        g_s[n] = ss; g_t[n] = tt;
    }
}

// ---------------- main fused HMMA kernel ----------------------------------------
extern __shared__ char dsm[];

__global__ __launch_bounds__(THREADS, 2)
void router_kernel(const float* __restrict__ H,      // [16384][2048]
                   const float* __restrict__ w_up,   // [8][64]
                   float* __restrict__ out)          // [16384][8]
{
    const uint32_t sb  = smem_u32(dsm);
    const int tid  = threadIdx.x;
    const int wid  = tid >> 5;
    const int lane = tid & 31;
    const int pos  = wid & 3;             // warp position: 2m x 2n
    const int wm   = pos & 1;             // rows wm*32..+32
    const int wn   = pos >> 1;            // cols wn*32..+32
    const int kh   = wid >> 2;            // k-half: k in [kh*32, kh*32+32) per tile

    // small tables
    ((float*)(dsm + O_WUP))[tid]       = w_up[tid];
    ((float*)(dsm + O_WUP))[tid + 256] = w_up[tid + 256];
    if (tid < BOT) {
        ((float*)(dsm + O_S))[tid] = g_s[tid];
        ((float*)(dsm + O_T))[tid] = g_t[tid];
    }

    // A geometry: 4 float4/thread/tile; rows lrow+16j, k quad (tid&15)
    const int lrow = tid >> 4;
    const float* Hbase = H + ((size_t)blockIdx.x * BM + lrow) * HIDDEN + (tid & 15) * 4;
    const uint32_t sts_sw = SWZ128((uint32_t)(lrow * 128 + (tid & 15) * 8));

    // Hoisted LDSM offsets: row term in bits>=7, k term bits 4-6 =>
    // SWZ128(row*128 + kb) == (SWZ128(row*128) ^ half16) ^ ks
    const uint32_t half16 = (uint32_t)((lane >> 4) * 16);
    uint32_t aoff[2], boff[2];
    #pragma unroll
    for (int mi = 0; mi < 2; mi++)
        aoff[mi] = SWZ128((uint32_t)((wm * 32 + mi * 16 + (lane & 15)) * 128)) ^ half16;
    #pragma unroll
    for (int g = 0; g < 2; g++)
        boff[g] = SWZ128((uint32_t)((wn * 32 + g * 16 + (lane & 15)) * 128)) ^ half16;

    float acc[2][4][4];                  // [mi][ni(n8)][reg] for 32x32 warp tile
    #pragma unroll
    for (int mi = 0; mi < 2; mi++)
        #pragma unroll
        for (int ni = 0; ni < 4; ni++)
            #pragma unroll
            for (int r = 0; r < 4; r++) acc[mi][ni][r] = 0.f;

    float psum[4] = {0.f, 0.f, 0.f, 0.f};
    float psq[4]  = {0.f, 0.f, 0.f, 0.f};
    float4 pf[4];

    // prologue: B0 via cp.async, A0 into regs
    cpa16(sb + B_HI(0) + tid * 16,         &g_Bhi4[tid]);
    cpa16(sb + B_HI(0) + (tid + 256) * 16, &g_Bhi4[tid + 256]);
    cpa16(sb + B_LO(0) + tid * 16,         &g_Blo4[tid]);
    cpa16(sb + B_LO(0) + (tid + 256) * 16, &g_Blo4[tid + 256]);
    CP_COMMIT();
    #pragma unroll
    for (int j = 0; j < 4; j++)
        pf[j] = *(const float4*)(Hbase + (size_t)j * 16 * HIDDEN);

    #pragma unroll 1
    for (int t = 0; t < NTILES; t++) {
        const int buf = t & 1;
        // ---- convert A_t regs -> hi/lo smem ----
        #pragma unroll
        for (int j = 0; j < 4; j++) {
            float4 v = pf[j];
            psum[j] += (v.x + v.y) + (v.z + v.w);
            psq[j]  = fmaf(v.x, v.x, psq[j]); psq[j] = fmaf(v.y, v.y, psq[j]);
            psq[j]  = fmaf(v.z, v.z, psq[j]); psq[j] = fmaf(v.w, v.w, psq[j]);
            __nv_bfloat162 h01 = __floats2bfloat162_rn(v.x, v.y);
            __nv_bfloat162 h23 = __floats2bfloat162_rn(v.z, v.w);
            float rx = v.x - __bfloat162float(h01.x);
            float ry = v.y - __bfloat162float(h01.y);
            float rz = v.z - __bfloat162float(h23.x);
            float rw = v.w - __bfloat162float(h23.y);
            __nv_bfloat162 l01 = __floats2bfloat162_rn(rx, ry);
            __nv_bfloat162 l23 = __floats2bfloat162_rn(rz, rw);
            uint32_t sw = sts_sw + (uint32_t)(j * 2048);
            *(uint2*)(dsm + A_HI(buf) + sw) = make_uint2(*(uint32_t*)&h01, *(uint32_t*)&h23);
            *(uint2*)(dsm + A_LO(buf) + sw) = make_uint2(*(uint32_t*)&l01, *(uint32_t*)&l23);
        }
        // ---- prefetch A_{t+1} (consumed next iter) ----
        if (t + 1 < NTILES) {
            const float* hp = Hbase + (t + 1) * BK;
            #pragma unroll
            for (int j = 0; j < 4; j++)
                pf[j] = *(const float4*)(hp + (size_t)j * 16 * HIDDEN);
        }
        CP_WAIT0();                 // B_t landed
        __syncthreads();            // A_t visible; MMA_{t-1} fully done
        // ---- issue B_{t+1} (safe: post-barrier) ----
        if (t + 1 < NTILES) {
            const uint4* srcH = g_Bhi4 + (t + 1) * 512;
            const uint4* srcL = g_Blo4 + (t + 1) * 512;
            const int nb = buf ^ 1;
            cpa16(sb + B_HI(nb) + tid * 16,         srcH + tid);
            cpa16(sb + B_HI(nb) + (tid + 256) * 16, srcH + tid + 256);
            cpa16(sb + B_LO(nb) + tid * 16,         srcL + tid);
            cpa16(sb + B_LO(nb) + (tid + 256) * 16, srcL + tid + 256);
            CP_COMMIT();
        }
        // ---- MMA over buf: this warp covers k in [kh*32, kh*32+32) ----
        const uint32_t ab_hi = sb + A_HI(buf), ab_lo = sb + A_LO(buf);
        const uint32_t bb_hi = sb + B_HI(buf), bb_lo = sb + B_LO(buf);
        #pragma unroll
        for (int ss = 0; ss < 2; ss++) {
            const uint32_t ks = (uint32_t)(kh * 64 + ss * 32);
            uint32_t ah[2][4], al[2][4], bh[2][4], bl[2][4];
            #pragma unroll
            for (int mi = 0; mi < 2; mi++) {
                LDMX4(ah[mi], ab_hi + (aoff[mi] ^ ks));
                LDMX4(al[mi], ab_lo + (aoff[mi] ^ ks));
            }
            #pragma unroll
            for (int g = 0; g < 2; g++) {
                LDMX4(bh[g], bb_hi + (boff[g] ^ ks));
                LDMX4(bl[g], bb_lo + (boff[g] ^ ks));
            }
            #pragma unroll
            for (int mi = 0; mi < 2; mi++)
                #pragma unroll
                for (int g = 0; g < 2; g++)
                    #pragma unroll
                    for (int h = 0; h < 2; h++) {
                        const int ni = g * 2 + h;
                        MMA16816(acc[mi][ni], ah[mi], bh[g][h], bh[g][h + 2]);
                        MMA16816(acc[mi][ni], ah[mi], bl[g][h], bl[g][h + 2]);
                        MMA16816(acc[mi][ni], al[mi], bh[g][h], bh[g][h + 2]);
                    }
        }
    }
    __syncthreads();    // all MMA done; smem reusable

    // ---- kh=1 warps dump k-partials (once per CTA) ----
    if (kh == 1) {
        float* pp = (float*)(dsm + O_PART) + pos * 1024;
        #pragma unroll
        for (int mi = 0; mi < 2; mi++)
            #pragma unroll
            for (int ni = 0; ni < 4; ni++)
                #pragma unroll
                for (int r = 0; r < 4; r++)
                    pp[((mi * 4 + ni) * 4 + r) * 32 + lane] = acc[mi][ni][r];
    }

    // ---- LN stats: groups of 16 consecutive lanes share a row ----
    #pragma unroll
    for (int o = 1; o < 16; o <<= 1) {
        #pragma unroll
        for (int j = 0; j < 4; j++) {
            psum[j] += __shfl_xor_sync(0xffffffffu, psum[j], o);
            psq[j]  += __shfl_xor_sync(0xffffffffu, psq[j], o);
        }
    }
    if ((tid & 15) == 0) {
        #pragma unroll
        for (int j = 0; j < 4; j++) {
            int row = j * 16 + lrow;
            float mu  = psum[j] * (1.f / HIDDEN);
            float var = psq[j] * (1.f / HIDDEN) - mu * mu;
            ((float*)(dsm + O_MU))[row] = mu;
            ((float*)(dsm + O_RS))[row] = rsqrtf(var + 1e-5f);
        }
    }
    __syncthreads();

    // ---- kh=0 warps: merge partials, LN-correct + SiLU -> z buffer ----
    if (kh == 0) {
        float* zb = (float*)dsm;             // [64][68] (A region, 17.4KB)
        const float* pp  = (const float*)(dsm + O_PART) + pos * 1024;
        const float* muA = (const float*)(dsm + O_MU);
        const float* rsA = (const float*)(dsm + O_RS);
        const float* sA  = (const float*)(dsm + O_S);
        const float* tA  = (const float*)(dsm + O_T);
        #pragma unroll
        for (int mi = 0; mi < 2; mi++) {
            int r0 = wm * 32 + mi * 16 + (lane >> 2);
            float mu0 = muA[r0], rs0 = rsA[r0];
            float mu1 = muA[r0 + 8], rs1 = rsA[r0 + 8];
            #pragma unroll
            for (int ni = 0; ni < 4; ni++) {
                const float* pf4 = pp + ((mi * 4 + ni) * 4) * 32 + lane;
                float a0 = acc[mi][ni][0] + pf4[0];
                float a1 = acc[mi][ni][1] + pf4[32];
                float a2 = acc[mi][ni][2] + pf4[64];
                float a3 = acc[mi][ni][3] + pf4[96];
                int c0 = wn * 32 + ni * 8 + (lane & 3) * 2;
                float s0 = sA[c0], s1 = sA[c0 + 1];
                float t0 = tA[c0], t1 = tA[c0 + 1];
                float p00 = rs0 * (a0 - mu0 * s0) + t0;
                float p01 = rs0 * (a1 - mu0 * s1) + t1;
                float p10 = rs1 * (a2 - mu1 * s0) + t0;
                float p11 = rs1 * (a3 - mu1 * s1) + t1;
                float z00 = p00 / (1.f + __expf(-p00));
                float z01 = p01 / (1.f + __expf(-p01));
                float z10 = p10 / (1.f + __expf(-p10));
                float z11 = p11 / (1.f + __expf(-p11));
                *(float2*)&zb[r0 * ZSTRIDE + c0]       = make_float2(z00, z01);
                *(float2*)&zb[(r0 + 8) * ZSTRIDE + c0] = make_float2(z10, z11);
            }
        }
    }
    __syncthreads();

    // ---- router GEMM: thread = (token m, expert pair eg) ----
    {
        const int m = tid & 63, eg = tid >> 6;
        const float* zr = (const float*)dsm + m * ZSTRIDE;
        const float* w0 = (const float*)(dsm + O_WUP) + eg * 128;
        const float* w1 = w0 + 64;
        float l0 = 0.f, l1 = 0.f;
        #pragma unroll
        for (int d4 = 0; d4 < 16; d4++) {
            float4 zv = ((const float4*)zr)[d4];
            float4 wa = ((const float4*)w0)[d4];
            float4 wb = ((const float4*)w1)[d4];
            l0 = fmaf(zv.x, wa.x, l0); l0 = fmaf(zv.y, wa.y, l0);
            l0 = fmaf(zv.z, wa.z, l0); l0 = fmaf(zv.w, wa.w, l0);
            l1 = fmaf(zv.x, wb.x, l1); l1 = fmaf(zv.y, wb.y, l1);
            l1 = fmaf(zv.z, wb.z, l1); l1 = fmaf(zv.w, wb.w, l1);
        }
        ((float*)(dsm + O_LG))[m * 8 + eg * 2]     = l0;
        ((float*)(dsm + O_LG))[m * 8 + eg * 2 + 1] = l1;
    }
    __syncthreads();

    // ---- top-2 softmax (first-index tie-break matches jax.lax.top_k) ----
    if (tid < BM) {
        const float* lp = (const float*)(dsm + O_LG) + tid * 8;
        float lg[8];
        #pragma unroll
        for (int e = 0; e < 8; e++) lg[e] = lp[e];
        int i1 = 0; float m1 = lg[0];
        #pragma unroll
        for (int e = 1; e < 8; e++) if (lg[e] > m1) { m1 = lg[e]; i1 = e; }
        int i2 = -1; float m2 = -3.4e38f;
        #pragma unroll
        for (int e = 0; e < 8; e++) if (e != i1 && lg[e] > m2) { m2 = lg[e]; i2 = e; }
        float p1 = 1.f / (1.f + __expf(m2 - m1));
        float p2 = 1.f - p1;
        float o[8];
        #pragma unroll
        for (int e = 0; e < 8; e++) o[e] = (e == i1) ? p1 : (e == i2) ? p2 : 0.f;
        float* op = out + ((size_t)blockIdx.x * BM + tid) * NEXP;
        *(float4*)op       = make_float4(o[0], o[1], o[2], o[3]);
        *(float4*)(op + 4) = make_float4(o[4], o[5], o[6], o[7]);
    }
}

// ---------------- launch --------------------------------------------------------
extern "C" void kernel_launch(void* const* d_in, const int* in_sizes, int n_in,
                              void* d_out, int out_size)
{
    (void)in_sizes; (void)n_in; (void)out_size;
    const float* hs     = (const float*)d_in[0];
    const float* w_down = (const float*)d_in[1];
    const float* w_up   = (const float*)d_in[2];
    const float* gamma  = (const float*)d_in[3];
    const float* beta   = (const float*)d_in[4];
    float* out = (float*)d_out;

    static int attr_done = 0;
    if (!attr_done) {
        cudaFuncSetAttribute(router_kernel, cudaFuncAttributeMaxDynamicSharedMemorySize, SMEM_TOTAL);
        attr_done = 1;
    }
    prep_kernel<<<BOT, THREADS>>>(w_down, gamma, beta);
    router_kernel<<<NBLK, THREADS, SMEM_TOTAL>>>(hs, w_up, out);
}

// round 10
// speedup vs baseline: 1.1416x; 1.0348x over previous
#include <cuda_runtime.h>
#include <cuda_bf16.h>
#include <math.h>
#include <stdint.h>

#define HIDDEN 2048
#define BOT    64
#define NEXP   8
#define NTOK   16384

#define BM       64
#define BK       64
#define NTILES   (HIDDEN / BK)       // 32
#define THREADS  256
#define NBLK     (NTOK / BM)         // 256

// ---------------- dynamic smem layout (byte offsets) ---------------------------
#define A_HI(b)   ((b) * 8192)                // 2 x 8KB (64 rows x 128B bf16)
#define A_LO(b)   (16384 + (b) * 8192)
#define B_HI(b)   (32768 + (b) * 8192)        // 2 x 8KB
#define B_LO(b)   (49152 + (b) * 8192)
#define O_PART    32768                       // 16KB k-partials (reuses B region post-loop)
#define O_MU      65536                       // 64 f32
#define O_RS      65792
#define O_S       66048
#define O_T       66304
#define O_WUP     66560                       // 2KB raw w_up [8][64]
#define O_LG      68608                       // 2KB logits [64][8]
#define SMEM_TOTAL 70656
#define ZSTRIDE   68

#define SWZ128(off) ((off) ^ (((off) >> 3) & 0x70))

// ---------------- device scratch (no allocations allowed) ----------------------
__device__ uint4 g_Bhi4[NTILES * 512];   // pre-swizzled bf16 hi tiles [n][k]
__device__ uint4 g_Blo4[NTILES * 512];   // lo tiles
__device__ float g_s[BOT];
__device__ float g_t[BOT];

// ---------------- PTX helpers ---------------------------------------------------
__device__ __forceinline__ uint32_t smem_u32(const void* p) {
    uint32_t a;
    asm("{ .reg .u64 t; cvta.to.shared.u64 t, %1; cvt.u32.u64 %0, t; }" : "=r"(a) : "l"(p));
    return a;
}
__device__ __forceinline__ void cpa16(uint32_t dst, const void* src) {
    asm volatile("cp.async.cg.shared.global [%0], [%1], 16;" :: "r"(dst), "l"(src));
}
#define CP_COMMIT() asm volatile("cp.async.commit_group;" ::: "memory")
#define CP_WAIT0()  asm volatile("cp.async.wait_group 0;" ::: "memory")

#define LDMX4(r, a) \
    asm volatile("ldmatrix.sync.aligned.m8n8.x4.shared.b16 {%0,%1,%2,%3}, [%4];" \
        : "=r"((r)[0]), "=r"((r)[1]), "=r"((r)[2]), "=r"((r)[3]) : "r"(a))

#define MMA16816(d, a, b0, b1) \
    asm volatile("mma.sync.aligned.m16n8k16.row.col.f32.bf16.bf16.f32 " \
        "{%0,%1,%2,%3}, {%4,%5,%6,%7}, {%8,%9}, {%0,%1,%2,%3};" \
        : "+f"((d)[0]), "+f"((d)[1]), "+f"((d)[2]), "+f"((d)[3]) \
        : "r"((a)[0]), "r"((a)[1]), "r"((a)[2]), "r"((a)[3]), "r"(b0), "r"(b1))

// ---------------- prep: split G = gamma*W into bf16 hi/lo, pre-swizzled ---------
__global__ void prep_kernel(const float* __restrict__ w_down,
                            const float* __restrict__ gamma,
                            const float* __restrict__ beta)
{
    __shared__ float red_s[8], red_t[8];
    const int n   = blockIdx.x;           // 0..63
    const int tid = threadIdx.x;          // 256
    const int k0  = tid * 8;

    float w[8], gv[8], bv[8];
    *(float4*)&w[0]  = *(const float4*)(w_down + n * HIDDEN + k0);
    *(float4*)&w[4]  = *(const float4*)(w_down + n * HIDDEN + k0 + 4);
    *(float4*)&gv[0] = *(const float4*)(gamma + k0);
    *(float4*)&gv[4] = *(const float4*)(gamma + k0 + 4);
    *(float4*)&bv[0] = *(const float4*)(beta + k0);
    *(float4*)&bv[4] = *(const float4*)(beta + k0 + 4);

    float ps = 0.f, pt = 0.f;
    uint32_t hih[4], loh[4];
    #pragma unroll
    for (int p = 0; p < 4; p++) {
        float g0 = gv[2*p] * w[2*p];
        float g1 = gv[2*p+1] * w[2*p+1];
        ps += g0 + g1;
        pt = fmaf(bv[2*p], w[2*p], pt);
        pt = fmaf(bv[2*p+1], w[2*p+1], pt);
        __nv_bfloat162 h = __floats2bfloat162_rn(g0, g1);
        float r0 = g0 - __bfloat162float(h.x);
        float r1 = g1 - __bfloat162float(h.y);
        __nv_bfloat162 l = __floats2bfloat162_rn(r0, r1);
        hih[p] = *(uint32_t*)&h;
        loh[p] = *(uint32_t*)&l;
    }
    const int tile = k0 >> 6, kk = k0 & 63;
    uint32_t off = (uint32_t)(n * 128 + kk * 2);     // 16B-aligned
    uint32_t sw  = SWZ128(off);
    *(uint4*)((char*)g_Bhi4 + tile * 8192 + sw) = make_uint4(hih[0], hih[1], hih[2], hih[3]);
    *(uint4*)((char*)g_Blo4 + tile * 8192 + sw) = make_uint4(loh[0], loh[1], loh[2], loh[3]);

    #pragma unroll
    for (int o = 16; o > 0; o >>= 1) {
        ps += __shfl_xor_sync(0xffffffffu, ps, o);
        pt += __shfl_xor_sync(0xffffffffu, pt, o);
    }
    int wi = tid >> 5, lane = tid & 31;
    if (lane == 0) { red_s[wi] = ps; red_t[wi] = pt; }
    __syncthreads();
    if (tid == 0) {
        float ss = 0.f, tt = 0.f;
        #pragma unroll
        for (int i = 0; i < 8; i++) { ss += red_s[i]; tt += red_t[i]; }
        g_s[n] = ss; g_t[n] = tt;
    }
}

// ---------------- main fused HMMA kernel ----------------------------------------
extern __shared__ char dsm[];

__global__ __launch_bounds__(THREADS, 2)
void router_kernel(const float* __restrict__ H,      // [16384][2048]
                   const float* __restrict__ w_up,   // [8][64]
                   float* __restrict__ out)          // [16384][8]
{
    const uint32_t sb  = smem_u32(dsm);
    const int tid  = threadIdx.x;
    const int wid  = tid >> 5;
    const int lane = tid & 31;
    const int pos  = wid & 3;             // warp position: 2m x 2n
    const int wm   = pos & 1;             // rows wm*32..+32
    const int wn   = pos >> 1;            // cols wn*32..+32
    const int kh   = wid >> 2;            // k-half within tile

    // small tables
    ((float*)(dsm + O_WUP))[tid]       = w_up[tid];
    ((float*)(dsm + O_WUP))[tid + 256] = w_up[tid + 256];
    if (tid < BOT) {
        ((float*)(dsm + O_S))[tid] = g_s[tid];
        ((float*)(dsm + O_T))[tid] = g_t[tid];
    }

    // A geometry: 4 float4/thread/tile; rows lrow+16j, k quad (tid&15)
    const int lrow = tid >> 4;
    const float* Hbase = H + ((size_t)blockIdx.x * BM + lrow) * HIDDEN + (tid & 15) * 4;
    const uint32_t sts_sw = SWZ128((uint32_t)(lrow * 128 + (tid & 15) * 8));

    // Hoisted LDSM offsets: SWZ128(row*128 + kb) == (SWZ128(row*128) ^ half16) ^ ks
    const uint32_t half16 = (uint32_t)((lane >> 4) * 16);
    uint32_t aoff[2], boff[2];
    #pragma unroll
    for (int mi = 0; mi < 2; mi++)
        aoff[mi] = SWZ128((uint32_t)((wm * 32 + mi * 16 + (lane & 15)) * 128)) ^ half16;
    #pragma unroll
    for (int g = 0; g < 2; g++)
        boff[g] = SWZ128((uint32_t)((wn * 32 + g * 16 + (lane & 15)) * 128)) ^ half16;

    float acc[2][4][4];                  // [mi][ni(n8)][reg] for 32x32 warp tile
    #pragma unroll
    for (int mi = 0; mi < 2; mi++)
        #pragma unroll
        for (int ni = 0; ni < 4; ni++)
            #pragma unroll
            for (int r = 0; r < 4; r++) acc[mi][ni][r] = 0.f;

    float psum[4] = {0.f, 0.f, 0.f, 0.f};
    float psq[4]  = {0.f, 0.f, 0.f, 0.f};
    float4 pf[4];

    // ---- prologue ----
    // B0 via cp.async
    cpa16(sb + B_HI(0) + tid * 16,         &g_Bhi4[tid]);
    cpa16(sb + B_HI(0) + (tid + 256) * 16, &g_Bhi4[tid + 256]);
    cpa16(sb + B_LO(0) + tid * 16,         &g_Blo4[tid]);
    cpa16(sb + B_LO(0) + (tid + 256) * 16, &g_Blo4[tid + 256]);
    CP_COMMIT();
    // A0 -> regs -> convert -> smem(0)
    #pragma unroll
    for (int j = 0; j < 4; j++)
        pf[j] = *(const float4*)(Hbase + (size_t)j * 16 * HIDDEN);
    #pragma unroll
    for (int j = 0; j < 4; j++) {
        float4 v = pf[j];
        psum[j] += (v.x + v.y) + (v.z + v.w);
        psq[j]  = fmaf(v.x, v.x, psq[j]); psq[j] = fmaf(v.y, v.y, psq[j]);
        psq[j]  = fmaf(v.z, v.z, psq[j]); psq[j] = fmaf(v.w, v.w, psq[j]);
        __nv_bfloat162 h01 = __floats2bfloat162_rn(v.x, v.y);
        __nv_bfloat162 h23 = __floats2bfloat162_rn(v.z, v.w);
        float rx = v.x - __bfloat162float(h01.x);
        float ry = v.y - __bfloat162float(h01.y);
        float rz = v.z - __bfloat162float(h23.x);
        float rw = v.w - __bfloat162float(h23.y);
        __nv_bfloat162 l01 = __floats2bfloat162_rn(rx, ry);
        __nv_bfloat162 l23 = __floats2bfloat162_rn(rz, rw);
        uint32_t sw = sts_sw + (uint32_t)(j * 2048);
        *(uint2*)(dsm + A_HI(0) + sw) = make_uint2(*(uint32_t*)&h01, *(uint32_t*)&h23);
        *(uint2*)(dsm + A_LO(0) + sw) = make_uint2(*(uint32_t*)&l01, *(uint32_t*)&l23);
    }
    // A1 -> regs (consumed inside iteration 0)
    #pragma unroll
    for (int j = 0; j < 4; j++)
        pf[j] = *(const float4*)(Hbase + BK + (size_t)j * 16 * HIDDEN);
    CP_WAIT0();
    __syncthreads();            // tile 0 (A+B) visible

    #pragma unroll 1
    for (int t = 0; t < NTILES; t++) {
        const int buf = t & 1, nb = buf ^ 1;
        // ---- issue B_{t+1} cp.async into nb (its last readers finished pre-barrier)
        if (t + 1 < NTILES) {
            const uint4* srcH = g_Bhi4 + (t + 1) * 512;
            const uint4* srcL = g_Blo4 + (t + 1) * 512;
            cpa16(sb + B_HI(nb) + tid * 16,         srcH + tid);
            cpa16(sb + B_HI(nb) + (tid + 256) * 16, srcH + tid + 256);
            cpa16(sb + B_LO(nb) + tid * 16,         srcL + tid);
            cpa16(sb + B_LO(nb) + (tid + 256) * 16, srcL + tid + 256);
            CP_COMMIT();
        }
        // ---- MMA phase for tile t on buf (3-pass hi/lo, split-k) ----
        {
            const uint32_t ab_hi = sb + A_HI(buf), ab_lo = sb + A_LO(buf);
            const uint32_t bb_hi = sb + B_HI(buf), bb_lo = sb + B_LO(buf);
            #pragma unroll
            for (int ss = 0; ss < 2; ss++) {
                const uint32_t ks = (uint32_t)(kh * 64 + ss * 32);
                uint32_t ah[2][4], al[2][4], bh[2][4], bl[2][4];
                #pragma unroll
                for (int mi = 0; mi < 2; mi++) {
                    LDMX4(ah[mi], ab_hi + (aoff[mi] ^ ks));
                    LDMX4(al[mi], ab_lo + (aoff[mi] ^ ks));
                }
                #pragma unroll
                for (int g = 0; g < 2; g++) {
                    LDMX4(bh[g], bb_hi + (boff[g] ^ ks));
                    LDMX4(bl[g], bb_lo + (boff[g] ^ ks));
                }
                #pragma unroll
                for (int mi = 0; mi < 2; mi++)
                    #pragma unroll
                    for (int g = 0; g < 2; g++)
                        #pragma unroll
                        for (int h = 0; h < 2; h++) {
                            const int ni = g * 2 + h;
                            MMA16816(acc[mi][ni], ah[mi], bh[g][h], bh[g][h + 2]);
                            MMA16816(acc[mi][ni], ah[mi], bl[g][h], bl[g][h + 2]);
                            MMA16816(acc[mi][ni], al[mi], bh[g][h], bh[g][h + 2]);
                        }
            }
        }
        // ---- convert A_{t+1} -> nb (overlaps tensor work of tile t) ----
        if (t + 1 < NTILES) {
            #pragma unroll
            for (int j = 0; j < 4; j++) {
                float4 v = pf[j];
                psum[j] += (v.x + v.y) + (v.z + v.w);
                psq[j]  = fmaf(v.x, v.x, psq[j]); psq[j] = fmaf(v.y, v.y, psq[j]);
                psq[j]  = fmaf(v.z, v.z, psq[j]); psq[j] = fmaf(v.w, v.w, psq[j]);
                __nv_bfloat162 h01 = __floats2bfloat162_rn(v.x, v.y);
                __nv_bfloat162 h23 = __floats2bfloat162_rn(v.z, v.w);
                float rx = v.x - __bfloat162float(h01.x);
                float ry = v.y - __bfloat162float(h01.y);
                float rz = v.z - __bfloat162float(h23.x);
                float rw = v.w - __bfloat162float(h23.y);
                __nv_bfloat162 l01 = __floats2bfloat162_rn(rx, ry);
                __nv_bfloat162 l23 = __floats2bfloat162_rn(rz, rw);
                uint32_t sw = sts_sw + (uint32_t)(j * 2048);
                *(uint2*)(dsm + A_HI(nb) + sw) = make_uint2(*(uint32_t*)&h01, *(uint32_t*)&h23);
                *(uint2*)(dsm + A_LO(nb) + sw) = make_uint2(*(uint32_t*)&l01, *(uint32_t*)&l23);
            }
        }
        // ---- prefetch A_{t+2} (pf now free; >1 iteration of slack) ----
        if (t + 2 < NTILES) {
            const float* hp = Hbase + (t + 2) * BK;
            #pragma unroll
            for (int j = 0; j < 4; j++)
                pf[j] = *(const float4*)(hp + (size_t)j * 16 * HIDDEN);
        }
        CP_WAIT0();                 // B_{t+1} landed
        __syncthreads();            // tile t reads done; tile t+1 smem visible
    }

    // ---- kh=1 warps dump k-partials (once per CTA) ----
    if (kh == 1) {
        float* pp = (float*)(dsm + O_PART) + pos * 1024;
        #pragma unroll
        for (int mi = 0; mi < 2; mi++)
            #pragma unroll
            for (int ni = 0; ni < 4; ni++)
                #pragma unroll
                for (int r = 0; r < 4; r++)
                    pp[((mi * 4 + ni) * 4 + r) * 32 + lane] = acc[mi][ni][r];
    }

    // ---- LN stats: groups of 16 consecutive lanes share a row ----
    #pragma unroll
    for (int o = 1; o < 16; o <<= 1) {
        #pragma unroll
        for (int j = 0; j < 4; j++) {
            psum[j] += __shfl_xor_sync(0xffffffffu, psum[j], o);
            psq[j]  += __shfl_xor_sync(0xffffffffu, psq[j], o);
        }
    }
    if ((tid & 15) == 0) {
        #pragma unroll
        for (int j = 0; j < 4; j++) {
            int row = j * 16 + lrow;
            float mu  = psum[j] * (1.f / HIDDEN);
            float var = psq[j] * (1.f / HIDDEN) - mu * mu;
            ((float*)(dsm + O_MU))[row] = mu;
            ((float*)(dsm + O_RS))[row] = rsqrtf(var + 1e-5f);
        }
    }
    __syncthreads();

    // ---- kh=0 warps: merge partials, LN-correct + SiLU -> z buffer ----
    if (kh == 0) {
        float* zb = (float*)dsm;             // [64][68] (A region)
        const float* pp  = (const float*)(dsm + O_PART) + pos * 1024;
        const float* muA = (const float*)(dsm + O_MU);
        const float* rsA = (const float*)(dsm + O_RS);
        const float* sA  = (const float*)(dsm + O_S);
        const float* tA  = (const float*)(dsm + O_T);
        #pragma unroll
        for (int mi = 0; mi < 2; mi++) {
            int r0 = wm * 32 + mi * 16 + (lane >> 2);
            float mu0 = muA[r0], rs0 = rsA[r0];
            float mu1 = muA[r0 + 8], rs1 = rsA[r0 + 8];
            #pragma unroll
            for (int ni = 0; ni < 4; ni++) {
                const float* pf4 = pp + ((mi * 4 + ni) * 4) * 32 + lane;
                float a0 = acc[mi][ni][0] + pf4[0];
                float a1 = acc[mi][ni][1] + pf4[32];
                float a2 = acc[mi][ni][2] + pf4[64];
                float a3 = acc[mi][ni][3] + pf4[96];
                int c0 = wn * 32 + ni * 8 + (lane & 3) * 2;
                float s0 = sA[c0], s1 = sA[c0 + 1];
                float t0 = tA[c0], t1 = tA[c0 + 1];
                float p00 = rs0 * (a0 - mu0 * s0) + t0;
                float p01 = rs0 * (a1 - mu0 * s1) + t1;
                float p10 = rs1 * (a2 - mu1 * s0) + t0;
                float p11 = rs1 * (a3 - mu1 * s1) + t1;
                float z00 = p00 / (1.f + __expf(-p00));
                float z01 = p01 / (1.f + __expf(-p01));
                float z10 = p10 / (1.f + __expf(-p10));
                float z11 = p11 / (1.f + __expf(-p11));
                *(float2*)&zb[r0 * ZSTRIDE + c0]       = make_float2(z00, z01);
                *(float2*)&zb[(r0 + 8) * ZSTRIDE + c0] = make_float2(z10, z11);
            }
        }
    }
    __syncthreads();

    // ---- router GEMM: thread = (token m, expert pair eg) ----
    {
        const int m = tid & 63, eg = tid >> 6;
        const float* zr = (const float*)dsm + m * ZSTRIDE;
        const float* w0 = (const float*)(dsm + O_WUP) + eg * 128;
        const float* w1 = w0 + 64;
        float l0 = 0.f, l1 = 0.f;
        #pragma unroll
        for (int d4 = 0; d4 < 16; d4++) {
            float4 zv = ((const float4*)zr)[d4];
            float4 wa = ((const float4*)w0)[d4];
            float4 wb = ((const float4*)w1)[d4];
            l0 = fmaf(zv.x, wa.x, l0); l0 = fmaf(zv.y, wa.y, l0);
            l0 = fmaf(zv.z, wa.z, l0); l0 = fmaf(zv.w, wa.w, l0);
            l1 = fmaf(zv.x, wb.x, l1); l1 = fmaf(zv.y, wb.y, l1);
            l1 = fmaf(zv.z, wb.z, l1); l1 = fmaf(zv.w, wb.w, l1);
        }
        ((float*)(dsm + O_LG))[m * 8 + eg * 2]     = l0;
        ((float*)(dsm + O_LG))[m * 8 + eg * 2 + 1] = l1;
    }
    __syncthreads();

    // ---- top-2 softmax (first-index tie-break matches jax.lax.top_k) ----
    if (tid < BM) {
        const float* lp = (const float*)(dsm + O_LG) + tid * 8;
        float lg[8];
        #pragma unroll
        for (int e = 0; e < 8; e++) lg[e] = lp[e];
        int i1 = 0; float m1 = lg[0];
        #pragma unroll
        for (int e = 1; e < 8; e++) if (lg[e] > m1) { m1 = lg[e]; i1 = e; }
        int i2 = -1; float m2 = -3.4e38f;
        #pragma unroll
        for (int e = 0; e < 8; e++) if (e != i1 && lg[e] > m2) { m2 = lg[e]; i2 = e; }
        float p1 = 1.f / (1.f + __expf(m2 - m1));
        float p2 = 1.f - p1;
        float o[8];
        #pragma unroll
        for (int e = 0; e < 8; e++) o[e] = (e == i1) ? p1 : (e == i2) ? p2 : 0.f;
        float* op = out + ((size_t)blockIdx.x * BM + tid) * NEXP;
        *(float4*)op       = make_float4(o[0], o[1], o[2], o[3]);
        *(float4*)(op + 4) = make_float4(o[4], o[5], o[6], o[7]);
    }
}

// ---------------- launch --------------------------------------------------------
extern "C" void kernel_launch(void* const* d_in, const int* in_sizes, int n_in,
                              void* d_out, int out_size)
{
    (void)in_sizes; (void)n_in; (void)out_size;
    const float* hs     = (const float*)d_in[0];
    const float* w_down = (const float*)d_in[1];
    const float* w_up   = (const float*)d_in[2];
    const float* gamma  = (const float*)d_in[3];
    const float* beta   = (const float*)d_in[4];
    float* out = (float*)d_out;

    static int attr_done = 0;
    if (!attr_done) {
        cudaFuncSetAttribute(router_kernel, cudaFuncAttributeMaxDynamicSharedMemorySize, SMEM_TOTAL);
        attr_done = 1;
    }
    prep_kernel<<<BOT, THREADS>>>(w_down, gamma, beta);
    router_kernel<<<NBLK, THREADS, SMEM_TOTAL>>>(hs, w_up, out);
}

// round 11
// speedup vs baseline: 1.1842x; 1.0373x over previous
#include <cuda_runtime.h>
#include <cuda_bf16.h>
#include <math.h>
#include <stdint.h>

#define HIDDEN 2048
#define BOT    64
#define NEXP   8
#define NTOK   16384

#define BM       64
#define BK       64
#define NTILES   (HIDDEN / BK)       // 32
#define THREADS  256
#define NBLK     (NTOK / BM)         // 256

// ---------------- dynamic smem layout (byte offsets) ---------------------------
#define A_HI(b)   ((b) * 8192)                // 2 x 8KB (64 rows x 128B bf16)
#define A_LO(b)   (16384 + (b) * 8192)        // 2 x 8KB
#define O_PART    0                           // 16KB k-partials (reuses A_HI post-loop)
#define O_ZB      16384                       // 17408B z buffer [64][68] (reuses A_LO)
#define O_MU      33792                       // 64 f32
#define O_RS      34048
#define O_S       34304
#define O_T       34560
#define O_WUP     34816                       // 2KB raw w_up [8][64]
#define O_LG      36864                       // 2KB logits [64][8]
#define SMEM_TOTAL 38912
#define ZSTRIDE   68

#define SWZ128(off) ((off) ^ (((off) >> 3) & 0x70))

// ---------------- device scratch (no allocations allowed) ----------------------
// B in mma.sync fragment order: index = ((k16blk*8 + n8blk)*32 + lane)*2 + reg
// (k16blk 0..127, n8blk 0..7, reg: 0 = k0-7 of block, 1 = k8-15)
__device__ uint32_t g_Bfh[128 * 8 * 32 * 2];   // 256KB hi fragments
__device__ uint32_t g_Bfl[128 * 8 * 32 * 2];   // 256KB lo fragments
__device__ float g_s[BOT];
__device__ float g_t[BOT];

// ---------------- PTX helpers ---------------------------------------------------
__device__ __forceinline__ uint32_t smem_u32(const void* p) {
    uint32_t a;
    asm("{ .reg .u64 t; cvta.to.shared.u64 t, %1; cvt.u32.u64 %0, t; }" : "=r"(a) : "l"(p));
    return a;
}
#define LDMX4(r, a) \
    asm volatile("ldmatrix.sync.aligned.m8n8.x4.shared.b16 {%0,%1,%2,%3}, [%4];" \
        : "=r"((r)[0]), "=r"((r)[1]), "=r"((r)[2]), "=r"((r)[3]) : "r"(a))

#define MMA16816(d, a, b0, b1) \
    asm volatile("mma.sync.aligned.m16n8k16.row.col.f32.bf16.bf16.f32 " \
        "{%0,%1,%2,%3}, {%4,%5,%6,%7}, {%8,%9}, {%0,%1,%2,%3};" \
        : "+f"((d)[0]), "+f"((d)[1]), "+f"((d)[2]), "+f"((d)[3]) \
        : "r"((a)[0]), "r"((a)[1]), "r"((a)[2]), "r"((a)[3]), "r"(b0), "r"(b1))

// ---------------- prep: G = gamma*W -> bf16 hi/lo in FRAGMENT order -------------
__global__ void prep_kernel(const float* __restrict__ w_down,
                            const float* __restrict__ gamma,
                            const float* __restrict__ beta)
{
    __shared__ float red_s[8], red_t[8];
    const int n   = blockIdx.x;           // 0..63
    const int tid = threadIdx.x;          // 256
    const int k0  = tid * 8;              // 8 consecutive k, aligned

    float w[8], gv[8], bv[8];
    *(float4*)&w[0]  = *(const float4*)(w_down + n * HIDDEN + k0);
    *(float4*)&w[4]  = *(const float4*)(w_down + n * HIDDEN + k0 + 4);
    *(float4*)&gv[0] = *(const float4*)(gamma + k0);
    *(float4*)&gv[4] = *(const float4*)(gamma + k0 + 4);
    *(float4*)&bv[0] = *(const float4*)(beta + k0);
    *(float4*)&bv[4] = *(const float4*)(beta + k0 + 4);

    float ps = 0.f, pt = 0.f;
    uint32_t hw[4], lw[4];
    #pragma unroll
    for (int p = 0; p < 4; p++) {
        float g0 = gv[2*p] * w[2*p];
        float g1 = gv[2*p+1] * w[2*p+1];
        ps += g0 + g1;
        pt = fmaf(bv[2*p], w[2*p], pt);
        pt = fmaf(bv[2*p+1], w[2*p+1], pt);
        __nv_bfloat162 h = __floats2bfloat162_rn(g0, g1);
        float r0 = g0 - __bfloat162float(h.x);
        float r1 = g1 - __bfloat162float(h.y);
        __nv_bfloat162 l = __floats2bfloat162_rn(r0, r1);
        hw[p] = *(uint32_t*)&h;
        lw[p] = *(uint32_t*)&l;
    }
    // fragment placement: lane = (n&7)*4 + p, reg = (k0>>3)&1, k16blk = k0>>4
    {
        const int k16  = k0 >> 4;
        const int n8   = n >> 3;
        const int l0   = (n & 7) * 4;
        const int reg  = (k0 >> 3) & 1;
        const int base = ((k16 * 8 + n8) * 32 + l0) * 2 + reg;
        #pragma unroll
        for (int p = 0; p < 4; p++) {
            g_Bfh[base + p * 2] = hw[p];
            g_Bfl[base + p * 2] = lw[p];
        }
    }

    #pragma unroll
    for (int o = 16; o > 0; o >>= 1) {
        ps += __shfl_xor_sync(0xffffffffu, ps, o);
        pt += __shfl_xor_sync(0xffffffffu, pt, o);
    }
    int wi = tid >> 5, lane = tid & 31;
    if (lane == 0) { red_s[wi] = ps; red_t[wi] = pt; }
    __syncthreads();
    if (tid == 0) {
        float ss = 0.f, tt = 0.f;
        #pragma unroll
        for (int i = 0; i < 8; i++) { ss += red_s[i]; tt += red_t[i]; }
        g_s[n] = ss; g_t[n] = tt;
    }
}

// ---------------- main fused HMMA kernel ----------------------------------------
extern __shared__ char dsm[];

__global__ __launch_bounds__(THREADS, 2)
void router_kernel(const float* __restrict__ H,      // [16384][2048]
                   const float* __restrict__ w_up,   // [8][64]
                   float* __restrict__ out)          // [16384][8]
{
    const uint32_t sb  = smem_u32(dsm);
    const int tid  = threadIdx.x;
    const int wid  = tid >> 5;
    const int lane = tid & 31;
    const int pos  = wid & 3;             // warp position: 2m x 2n
    const int wm   = pos & 1;             // rows wm*32..+32
    const int wn   = pos >> 1;            // cols wn*32..+32
    const int kh   = wid >> 2;            // k-half within tile

    // small tables
    ((float*)(dsm + O_WUP))[tid]       = w_up[tid];
    ((float*)(dsm + O_WUP))[tid + 256] = w_up[tid + 256];
    if (tid < BOT) {
        ((float*)(dsm + O_S))[tid] = g_s[tid];
        ((float*)(dsm + O_T))[tid] = g_t[tid];
    }

    // A geometry: 4 float4/thread/tile; rows lrow+16j, k quad (tid&15)
    const int lrow = tid >> 4;
    const float* Hbase = H + ((size_t)blockIdx.x * BM + lrow) * HIDDEN + (tid & 15) * 4;
    const uint32_t sts_sw = SWZ128((uint32_t)(lrow * 128 + (tid & 15) * 8));

    // Hoisted A-LDSM offsets: SWZ128(row*128 + kb) == (SWZ128(row*128) ^ half16) ^ ks
    const uint32_t half16 = (uint32_t)((lane >> 4) * 16);
    uint32_t aoff[2];
    #pragma unroll
    for (int mi = 0; mi < 2; mi++)
        aoff[mi] = SWZ128((uint32_t)((wm * 32 + mi * 16 + (lane & 15)) * 128)) ^ half16;

    // B fragment base for this warp (per tile: + t*4*512)
    const uint32_t bfbase = (uint32_t)(((kh * 2) * 8 + wn * 4) * 32 + lane) * 2;

    float acc[2][4][4];                  // [mi][n8][reg] for 32x32 warp tile
    #pragma unroll
    for (int mi = 0; mi < 2; mi++)
        #pragma unroll
        for (int ni = 0; ni < 4; ni++)
            #pragma unroll
            for (int r = 0; r < 4; r++) acc[mi][ni][r] = 0.f;

    float psum[4] = {0.f, 0.f, 0.f, 0.f};
    float psq[4]  = {0.f, 0.f, 0.f, 0.f};
    float4 pf[4];

    // ---- prologue: A0 -> regs -> convert -> smem(0); A1 -> pf ----
    #pragma unroll
    for (int j = 0; j < 4; j++)
        pf[j] = *(const float4*)(Hbase + (size_t)j * 16 * HIDDEN);
    #pragma unroll
    for (int j = 0; j < 4; j++) {
        float4 v = pf[j];
        psum[j] += (v.x + v.y) + (v.z + v.w);
        psq[j]  = fmaf(v.x, v.x, psq[j]); psq[j] = fmaf(v.y, v.y, psq[j]);
        psq[j]  = fmaf(v.z, v.z, psq[j]); psq[j] = fmaf(v.w, v.w, psq[j]);
        __nv_bfloat162 h01 = __floats2bfloat162_rn(v.x, v.y);
        __nv_bfloat162 h23 = __floats2bfloat162_rn(v.z, v.w);
        float rx = v.x - __bfloat162float(h01.x);
        float ry = v.y - __bfloat162float(h01.y);
        float rz = v.z - __bfloat162float(h23.x);
        float rw = v.w - __bfloat162float(h23.y);
        __nv_bfloat162 l01 = __floats2bfloat162_rn(rx, ry);
        __nv_bfloat162 l23 = __floats2bfloat162_rn(rz, rw);
        uint32_t sw = sts_sw + (uint32_t)(j * 2048);
        *(uint2*)(dsm + A_HI(0) + sw) = make_uint2(*(uint32_t*)&h01, *(uint32_t*)&h23);
        *(uint2*)(dsm + A_LO(0) + sw) = make_uint2(*(uint32_t*)&l01, *(uint32_t*)&l23);
    }
    #pragma unroll
    for (int j = 0; j < 4; j++)
        pf[j] = *(const float4*)(Hbase + BK + (size_t)j * 16 * HIDDEN);
    __syncthreads();            // tile 0 A visible

    #pragma unroll 1
    for (int t = 0; t < NTILES; t++) {
        const int buf = t & 1, nb = buf ^ 1;
        // ---- B fragments for tile t: 16 coalesced LDG.64 (MLP 16) ----
        uint2 bh2[2][4], bl2[2][4];
        {
            const uint32_t tb = bfbase + (uint32_t)t * 2048;   // t*4 k16blks * 512
            #pragma unroll
            for (int ss = 0; ss < 2; ss++) {
                const uint32_t o = tb + (uint32_t)ss * 512;
                #pragma unroll
                for (int j = 0; j < 4; j++) {
                    bh2[ss][j] = *(const uint2*)&g_Bfh[o + j * 64];
                    bl2[ss][j] = *(const uint2*)&g_Bfl[o + j * 64];
                }
            }
        }
        // ---- MMA phase for tile t on buf (3-pass hi/lo, split-k) ----
        {
            const uint32_t ab_hi = sb + A_HI(buf), ab_lo = sb + A_LO(buf);
            #pragma unroll
            for (int ss = 0; ss < 2; ss++) {
                const uint32_t ks = (uint32_t)(kh * 64 + ss * 32);
                uint32_t ah[2][4], al[2][4];
                #pragma unroll
                for (int mi = 0; mi < 2; mi++) {
                    LDMX4(ah[mi], ab_hi + (aoff[mi] ^ ks));
                    LDMX4(al[mi], ab_lo + (aoff[mi] ^ ks));
                }
                #pragma unroll
                for (int mi = 0; mi < 2; mi++)
                    #pragma unroll
                    for (int ni = 0; ni < 4; ni++) {
                        MMA16816(acc[mi][ni], ah[mi], bh2[ss][ni].x, bh2[ss][ni].y);
                        MMA16816(acc[mi][ni], ah[mi], bl2[ss][ni].x, bl2[ss][ni].y);
                        MMA16816(acc[mi][ni], al[mi], bh2[ss][ni].x, bh2[ss][ni].y);
                    }
            }
        }
        // ---- convert A_{t+1} -> nb (overlaps tensor work of tile t) ----
        if (t + 1 < NTILES) {
            #pragma unroll
            for (int j = 0; j < 4; j++) {
                float4 v = pf[j];
                psum[j] += (v.x + v.y) + (v.z + v.w);
                psq[j]  = fmaf(v.x, v.x, psq[j]); psq[j] = fmaf(v.y, v.y, psq[j]);
                psq[j]  = fmaf(v.z, v.z, psq[j]); psq[j] = fmaf(v.w, v.w, psq[j]);
                __nv_bfloat162 h01 = __floats2bfloat162_rn(v.x, v.y);
                __nv_bfloat162 h23 = __floats2bfloat162_rn(v.z, v.w);
                float rx = v.x - __bfloat162float(h01.x);
                float ry = v.y - __bfloat162float(h01.y);
                float rz = v.z - __bfloat162float(h23.x);
                float rw = v.w - __bfloat162float(h23.y);
                __nv_bfloat162 l01 = __floats2bfloat162_rn(rx, ry);
                __nv_bfloat162 l23 = __floats2bfloat162_rn(rz, rw);
                uint32_t sw = sts_sw + (uint32_t)(j * 2048);
                *(uint2*)(dsm + A_HI(nb) + sw) = make_uint2(*(uint32_t*)&h01, *(uint32_t*)&h23);
                *(uint2*)(dsm + A_LO(nb) + sw) = make_uint2(*(uint32_t*)&l01, *(uint32_t*)&l23);
            }
        }
        // ---- prefetch A_{t+2} (pf free; >1 iteration of slack) ----
        if (t + 2 < NTILES) {
            const float* hp = Hbase + (t + 2) * BK;
            #pragma unroll
            for (int j = 0; j < 4; j++)
                pf[j] = *(const float4*)(hp + (size_t)j * 16 * HIDDEN);
        }
        __syncthreads();            // tile t A reads done; tile t+1 A visible
    }

    // ---- kh=1 warps dump k-partials (once per CTA) ----
    if (kh == 1) {
        float* pp = (float*)(dsm + O_PART) + pos * 1024;
        #pragma unroll
        for (int mi = 0; mi < 2; mi++)
            #pragma unroll
            for (int ni = 0; ni < 4; ni++)
                #pragma unroll
                for (int r = 0; r < 4; r++)
                    pp[((mi * 4 + ni) * 4 + r) * 32 + lane] = acc[mi][ni][r];
    }

    // ---- LN stats: groups of 16 consecutive lanes share a row ----
    #pragma unroll
    for (int o = 1; o < 16; o <<= 1) {
        #pragma unroll
        for (int j = 0; j < 4; j++) {
            psum[j] += __shfl_xor_sync(0xffffffffu, psum[j], o);
            psq[j]  += __shfl_xor_sync(0xffffffffu, psq[j], o);
        }
    }
    if ((tid & 15) == 0) {
        #pragma unroll
        for (int j = 0; j < 4; j++) {
            int row = j * 16 + lrow;
            float mu  = psum[j] * (1.f / HIDDEN);
            float var = psq[j] * (1.f / HIDDEN) - mu * mu;
            ((float*)(dsm + O_MU))[row] = mu;
            ((float*)(dsm + O_RS))[row] = rsqrtf(var + 1e-5f);
        }
    }
    __syncthreads();

    // ---- kh=0 warps: merge partials, LN-correct + SiLU -> z buffer ----
    if (kh == 0) {
        float* zb = (float*)(dsm + O_ZB);    // [64][68]
        const float* pp  = (const float*)(dsm + O_PART) + pos * 1024;
        const float* muA = (const float*)(dsm + O_MU);
        const float* rsA = (const float*)(dsm + O_RS);
        const float* sA  = (const float*)(dsm + O_S);
        const float* tA  = (const float*)(dsm + O_T);
        #pragma unroll
        for (int mi = 0; mi < 2; mi++) {
            int r0 = wm * 32 + mi * 16 + (lane >> 2);
            float mu0 = muA[r0], rs0 = rsA[r0];
            float mu1 = muA[r0 + 8], rs1 = rsA[r0 + 8];
            #pragma unroll
            for (int ni = 0; ni < 4; ni++) {
                const float* pf4 = pp + ((mi * 4 + ni) * 4) * 32 + lane;
                float a0 = acc[mi][ni][0] + pf4[0];
                float a1 = acc[mi][ni][1] + pf4[32];
                float a2 = acc[mi][ni][2] + pf4[64];
                float a3 = acc[mi][ni][3] + pf4[96];
                int c0 = wn * 32 + ni * 8 + (lane & 3) * 2;
                float s0 = sA[c0], s1 = sA[c0 + 1];
                float t0 = tA[c0], t1 = tA[c0 + 1];
                float p00 = rs0 * (a0 - mu0 * s0) + t0;
                float p01 = rs0 * (a1 - mu0 * s1) + t1;
                float p10 = rs1 * (a2 - mu1 * s0) + t0;
                float p11 = rs1 * (a3 - mu1 * s1) + t1;
                float z00 = p00 / (1.f + __expf(-p00));
                float z01 = p01 / (1.f + __expf(-p01));
                float z10 = p10 / (1.f + __expf(-p10));
                float z11 = p11 / (1.f + __expf(-p11));
                *(float2*)&zb[r0 * ZSTRIDE + c0]       = make_float2(z00, z01);
                *(float2*)&zb[(r0 + 8) * ZSTRIDE + c0] = make_float2(z10, z11);
            }
        }
    }
    __syncthreads();

    // ---- router GEMM: thread = (token m, expert pair eg) ----
    {
        const int m = tid & 63, eg = tid >> 6;
        const float* zr = (const float*)(dsm + O_ZB) + m * ZSTRIDE;
        const float* w0 = (const float*)(dsm + O_WUP) + eg * 128;
        const float* w1 = w0 + 64;
        float l0 = 0.f, l1 = 0.f;
        #pragma unroll
        for (int d4 = 0; d4 < 16; d4++) {
            float4 zv = ((const float4*)zr)[d4];
            float4 wa = ((const float4*)w0)[d4];
            float4 wb = ((const float4*)w1)[d4];
            l0 = fmaf(zv.x, wa.x, l0); l0 = fmaf(zv.y, wa.y, l0);
            l0 = fmaf(zv.z, wa.z, l0); l0 = fmaf(zv.w, wa.w, l0);
            l1 = fmaf(zv.x, wb.x, l1); l1 = fmaf(zv.y, wb.y, l1);
            l1 = fmaf(zv.z, wb.z, l1); l1 = fmaf(zv.w, wb.w, l1);
        }
        ((float*)(dsm + O_LG))[m * 8 + eg * 2]     = l0;
        ((float*)(dsm + O_LG))[m * 8 + eg * 2 + 1] = l1;
    }
    __syncthreads();

    // ---- top-2 softmax (first-index tie-break matches jax.lax.top_k) ----
    if (tid < BM) {
        const float* lp = (const float*)(dsm + O_LG) + tid * 8;
        float lg[8];
        #pragma unroll
        for (int e = 0; e < 8; e++) lg[e] = lp[e];
        int i1 = 0; float m1 = lg[0];
        #pragma unroll
        for (int e = 1; e < 8; e++) if (lg[e] > m1) { m1 = lg[e]; i1 = e; }
        int i2 = -1; float m2 = -3.4e38f;
        #pragma unroll
        for (int e = 0; e < 8; e++) if (e != i1 && lg[e] > m2) { m2 = lg[e]; i2 = e; }
        float p1 = 1.f / (1.f + __expf(m2 - m1));
        float p2 = 1.f - p1;
        float o[8];
        #pragma unroll
        for (int e = 0; e < 8; e++) o[e] = (e == i1) ? p1 : (e == i2) ? p2 : 0.f;
        float* op = out + ((size_t)blockIdx.x * BM + tid) * NEXP;
        *(float4*)op       = make_float4(o[0], o[1], o[2], o[3]);
        *(float4*)(op + 4) = make_float4(o[4], o[5], o[6], o[7]);
    }
}

// ---------------- launch --------------------------------------------------------
extern "C" void kernel_launch(void* const* d_in, const int* in_sizes, int n_in,
                              void* d_out, int out_size)
{
    (void)in_sizes; (void)n_in; (void)out_size;
    const float* hs     = (const float*)d_in[0];
    const float* w_down = (const float*)d_in[1];
    const float* w_up   = (const float*)d_in[2];
    const float* gamma  = (const float*)d_in[3];
    const float* beta   = (const float*)d_in[4];
    float* out = (float*)d_out;

    static int attr_done = 0;
    if (!attr_done) {
        cudaFuncSetAttribute(router_kernel, cudaFuncAttributeMaxDynamicSharedMemorySize, SMEM_TOTAL);
        attr_done = 1;
    }
    prep_kernel<<<BOT, THREADS>>>(w_down, gamma, beta);
    router_kernel<<<NBLK, THREADS, SMEM_TOTAL>>>(hs, w_up, out);
}